// round 14
// baseline (speedup 1.0000x reference)
#include <cuda_runtime.h>
#include <cuda_fp16.h>
#include <math.h>
#include <stdint.h>

#define BB 2
#define SS 2048
#define DD 1024
#define HH 16
#define DKK 64

// ---------------------------------------------------------------------------
// Scratch
// ---------------------------------------------------------------------------
static __device__ __half h_x[3][BB * SS * DD];     // converted inputs q,k,v
static __device__ __half h_wt[3][DD * DD];         // W^T [n][k] half
static __device__ __half g_qh[BB * SS * DD];       // Q proj [token][D]
static __device__ __half g_kh[BB * SS * DD];       // K proj [token][D]
static __device__ __half g_vth[BB * HH * DKK * SS];// V^T [B,H,DK,S]
static __device__ float  g_rl[BB * HH * SS];       // softmax row sums
static __device__ float  g_o[BB * SS * DD];        // attention out (f32)
static __device__ uint32_t g_mb[BB * SS * (SS / 32)]; // packed mask bits

// ---------------------------------------------------------------------------
// helpers
// ---------------------------------------------------------------------------
__device__ __forceinline__ uint32_t smem_u32(const void* p) {
    uint32_t a;
    asm("{ .reg .u64 t; cvta.to.shared.u64 t, %1; cvt.u32.u64 %0, t; }"
        : "=r"(a) : "l"(p));
    return a;
}
__device__ __forceinline__ void mma_f16(float* d, const uint32_t* a, const uint32_t* b) {
    asm volatile(
        "mma.sync.aligned.m16n8k16.row.col.f32.f16.f16.f32 "
        "{%0,%1,%2,%3}, {%4,%5,%6,%7}, {%8,%9}, {%0,%1,%2,%3};"
        : "+f"(d[0]), "+f"(d[1]), "+f"(d[2]), "+f"(d[3])
        : "r"(a[0]), "r"(a[1]), "r"(a[2]), "r"(a[3]), "r"(b[0]), "r"(b[1]));
}
__device__ __forceinline__ void ldsm_x4(uint32_t* r, uint32_t addr) {
    asm volatile("ldmatrix.sync.aligned.m8n8.x4.shared.b16 {%0,%1,%2,%3}, [%4];"
        : "=r"(r[0]), "=r"(r[1]), "=r"(r[2]), "=r"(r[3]) : "r"(addr));
}
__device__ __forceinline__ uint32_t pack_h2(float a, float b) {
    __half2 h = __floats2half2_rn(a, b);
    return *(uint32_t*)&h;
}
#define CP_ASYNC16(smem, gptr) \
    asm volatile("cp.async.ca.shared.global [%0], [%1], 16;" :: "r"(smem), "l"(gptr))
#define CP_COMMIT() asm volatile("cp.async.commit_group;" ::: "memory")
#define CP_WAIT(n)  asm volatile("cp.async.wait_group %0;" :: "n"(n) : "memory")

extern __shared__ uint32_t dynsm[];

// ---------------------------------------------------------------------------
// Pack mask bytes -> bits
// ---------------------------------------------------------------------------
__global__ __launch_bounds__(256) void maskpack_kernel(const unsigned char* __restrict__ mask)
{
    int idx = blockIdx.x * 256 + threadIdx.x;
    const uint32_t* src = (const uint32_t*)(mask + (size_t)idx * 32);
    uint32_t bits = 0;
#pragma unroll
    for (int i = 0; i < 8; i++) {
        uint32_t w = src[i];
#pragma unroll
        for (int j = 0; j < 4; j++)
            if ((w >> (8 * j)) & 0xFF) bits |= 1u << (4 * i + j);
    }
    g_mb[idx] = bits;
}

// ---------------------------------------------------------------------------
// Convert inputs f32 -> half
// ---------------------------------------------------------------------------
__global__ __launch_bounds__(256) void cvt_kernel(
    const float* __restrict__ q, const float* __restrict__ k, const float* __restrict__ v)
{
    int z = blockIdx.y;
    const float* src = (z == 0) ? q : (z == 1) ? k : v;
    __half* dst = h_x[z];
    size_t i = ((size_t)blockIdx.x * 256 + threadIdx.x) * 8;
    float4 a = *(const float4*)&src[i];
    float4 b = *(const float4*)&src[i + 4];
    uint4 o;
    o.x = pack_h2(a.x, a.y); o.y = pack_h2(a.z, a.w);
    o.z = pack_h2(b.x, b.y); o.w = pack_h2(b.z, b.w);
    *(uint4*)&dst[i] = o;
}

// ---------------------------------------------------------------------------
// W transpose -> half
// ---------------------------------------------------------------------------
__global__ __launch_bounds__(256) void wt_kernel(
    const float* __restrict__ Wq, const float* __restrict__ Wk, const float* __restrict__ Wv)
{
    __shared__ float t[32][33];
    int z = blockIdx.z;
    const float* W = (z == 0) ? Wq : (z == 1) ? Wk : Wv;
    __half* O = h_wt[z];
    int x0 = blockIdx.x * 32, y0 = blockIdx.y * 32;
    int tx = threadIdx.x & 31, ty = threadIdx.x >> 5;
#pragma unroll
    for (int i = 0; i < 4; i++)
        t[ty + 8 * i][tx] = W[(size_t)(y0 + ty + 8 * i) * DD + x0 + tx];
    __syncthreads();
#pragma unroll
    for (int i = 0; i < 4; i++)
        O[(size_t)(x0 + ty + 8 * i) * DD + y0 + tx] = __float2half_rn(t[tx][ty + 8 * i]);
}

// ---------------------------------------------------------------------------
// Projections (fp16): block 128m x 128n, BK=64 stages, 8 warps (4m x 2n),
// warp 32x64, 2 blocks/SM.
// ---------------------------------------------------------------------------
#define PJ_ST 72                            // halves per row (64 + 8 pad)
#define PJ_STAGEH ((128 + 128) * PJ_ST)     // halves per stage
#define PJ_SMEM (2 * PJ_STAGEH * 2)         // 73728 bytes

__global__ __launch_bounds__(256, 2) void proj_f16()
{
    int tid = threadIdx.x, wid = tid >> 5, lane = tid & 31;
    int z = blockIdx.z;
    const __half* X = h_x[z];
    const __half* WT = h_wt[z];
    int m0 = blockIdx.y * 128, n0 = blockIdx.x * 128;
    uint32_t sb = smem_u32(dynsm);

    int arow = tid >> 1, ach = (tid & 1) * 32;
    const __half* srcA = X + (size_t)(m0 + arow) * DD + ach;
    uint32_t dstA = sb + (arow * PJ_ST + ach) * 2;
    const __half* srcB = WT + (size_t)(n0 + arow) * DD + ach;
    uint32_t dstB = sb + ((128 + arow) * PJ_ST + ach) * 2;

#define PJF_ISSUE(st) do {                                                 \
        uint32_t so_ = ((st) & 1) * (PJ_STAGEH * 2);                       \
        const __half* a_ = srcA + (st) * 64;                               \
        const __half* b_ = srcB + (st) * 64;                               \
        _Pragma("unroll")                                                  \
        for (int j_ = 0; j_ < 4; j_++) {                                   \
            CP_ASYNC16(dstA + so_ + j_ * 16, a_ + j_ * 8);                 \
            CP_ASYNC16(dstB + so_ + j_ * 16, b_ + j_ * 8);                 \
        }                                                                  \
    } while (0)

    PJF_ISSUE(0); CP_COMMIT();
    PJF_ISSUE(1); CP_COMMIT();

    int wm = (wid & 3) * 32, wn = (wid >> 2) * 64;
    uint32_t aoff0 = ((wm + (lane & 15)) * PJ_ST) * 2 + (lane >> 4) * 16;
    uint32_t aoff1 = ((wm + 16 + (lane & 15)) * PJ_ST) * 2 + (lane >> 4) * 16;
    uint32_t boff = ((128 + wn + (lane & 15)) * PJ_ST) * 2 + (lane >> 4) * 16;

    float acc[2][8][4] = {};

    for (int it = 0; it < 16; ++it) {
        CP_WAIT(1);
        __syncthreads();
        uint32_t so = (it & 1) * (PJ_STAGEH * 2);
#pragma unroll
        for (int ks = 0; ks < 4; ks++) {
            uint32_t af[2][4];
            ldsm_x4(af[0], sb + so + aoff0 + ks * 32);
            ldsm_x4(af[1], sb + so + aoff1 + ks * 32);
#pragma unroll
            for (int t = 0; t < 4; t++) {
                uint32_t bb[4];
                ldsm_x4(bb, sb + so + boff + (16 * t * PJ_ST) * 2 + ks * 32);
                uint32_t bf0[2] = { bb[0], bb[2] };
                uint32_t bf1[2] = { bb[1], bb[3] };
#pragma unroll
                for (int i = 0; i < 2; i++) {
                    mma_f16(acc[i][2 * t], af[i], bf0);
                    mma_f16(acc[i][2 * t + 1], af[i], bf1);
                }
            }
        }
        __syncthreads();
        if (it + 2 < 16) PJF_ISSUE(it + 2);
        CP_COMMIT();
    }

    int g = lane >> 2, tig = lane & 3;
    if (z < 2) {
        __half* O = (z == 0) ? g_qh : g_kh;
#pragma unroll
        for (int i = 0; i < 2; i++) {
            int r0 = m0 + wm + 16 * i + g;
#pragma unroll
            for (int j = 0; j < 8; j++) {
                int c = n0 + wn + 8 * j + 2 * tig;
                *(uint32_t*)&O[(size_t)r0 * DD + c] = pack_h2(acc[i][j][0], acc[i][j][1]);
                *(uint32_t*)&O[(size_t)(r0 + 8) * DD + c] = pack_h2(acc[i][j][2], acc[i][j][3]);
            }
        }
    } else {
        int h = (n0 + wn) >> 6;
#pragma unroll
        for (int i = 0; i < 2; i++) {
            int r0 = m0 + wm + 16 * i + g;
#pragma unroll
            for (int j = 0; j < 8; j++) {
                int dk = 8 * j + 2 * tig;
#pragma unroll
                for (int e = 0; e < 4; e++) {
                    int gm = r0 + (e >> 1) * 8;
                    int b = gm >> 11, s = gm & 2047;
                    g_vth[(((size_t)(b * HH + h)) * DKK + dk + (e & 1)) * SS + s] =
                        __float2half_rn(acc[i][j][e]);
                }
            }
        }
    }
}

// ---------------------------------------------------------------------------
// Flash pass 1: row sums l = sum_k e^{s/8}. 256 q rows/block, 8 warps of 32 q.
// ---------------------------------------------------------------------------
#define FL_ST 72
#define QT1_BYTES (256 * FL_ST * 2)         // 36864
#define KT_BYTES (128 * FL_ST * 2)          // 18432
#define P1_SMEM (QT1_BYTES + 2 * KT_BYTES)  // 73728

__global__ __launch_bounds__(256, 2) void pass1_kernel()
{
    int tid = threadIdx.x, wid = tid >> 5, lane = tid & 31;
    int g = lane >> 2, tig = lane & 3;
    int q0 = blockIdx.x * 256, bh = blockIdx.y;
    int b = bh >> 4, h = bh & 15;
    uint32_t sb = smem_u32(dynsm);

    {   // Q fill: one row per thread — full 64 halves = 8 x 16B
        const __half* s = g_qh + (size_t)(b * SS + q0 + tid) * DD + h * 64;
        uint32_t d = sb + (tid * FL_ST) * 2;
#pragma unroll
        for (int j = 0; j < 8; j++) CP_ASYNC16(d + j * 16, s + j * 8);
    }
    int krow = tid >> 1, kch = (tid & 1) * 32;
    const __half* srcK = g_kh + (size_t)(b * SS + krow) * DD + h * 64 + kch;
    uint32_t dstK = sb + QT1_BYTES + (krow * FL_ST + kch) * 2;

#define K1_ISSUE(st) do {                                                  \
        uint32_t so_ = ((st) & 1) * KT_BYTES;                              \
        const __half* s_ = srcK + (size_t)(st) * 128 * DD;                 \
        _Pragma("unroll")                                                  \
        for (int j_ = 0; j_ < 4; j_++)                                     \
            CP_ASYNC16(dstK + so_ + j_ * 16, s_ + j_ * 8);                 \
    } while (0)

    K1_ISSUE(0); CP_COMMIT();
    K1_ISSUE(1); CP_COMMIT();

    uint32_t qoff0 = ((32 * wid + (lane & 15)) * FL_ST) * 2 + (lane >> 4) * 16;
    uint32_t qoff1 = ((32 * wid + 16 + (lane & 15)) * FL_ST) * 2 + (lane >> 4) * 16;
    uint32_t koff = ((lane & 15) * FL_ST) * 2 + (lane >> 4) * 16;

    int qg = q0 + 32 * wid + g;
    const uint32_t* mbp[4];
#pragma unroll
    for (int r = 0; r < 4; r++)
        mbp[r] = g_mb + (size_t)(b * SS + qg + 8 * r) * 64;
    int bsh = 2 * tig;

    uint32_t qf[2][4][4];
    float sums[4] = { 0.f, 0.f, 0.f, 0.f };

    for (int it = 0; it < 16; ++it) {
        CP_WAIT(1);
        __syncthreads();
        if (it == 0) {
#pragma unroll
            for (int kk = 0; kk < 4; kk++) {
                ldsm_x4(qf[0][kk], sb + qoff0 + kk * 32);
                ldsm_x4(qf[1][kk], sb + qoff1 + kk * 32);
            }
        }
        uint32_t so = QT1_BYTES + (it & 1) * KT_BYTES;
        uint4 mw[4];
#pragma unroll
        for (int r = 0; r < 4; r++) mw[r] = *(const uint4*)&mbp[r][it * 4];

#pragma unroll
        for (int t = 0; t < 8; t++) {
            float a2[2][2][4] = {};
#pragma unroll
            for (int kk = 0; kk < 4; kk++) {
                uint32_t bb[4];
                ldsm_x4(bb, sb + so + koff + (16 * t * FL_ST) * 2 + kk * 32);
                uint32_t bf0[2] = { bb[0], bb[2] };
                uint32_t bf1[2] = { bb[1], bb[3] };
#pragma unroll
                for (int mt = 0; mt < 2; mt++) {
                    mma_f16(a2[mt][0], qf[mt][kk], bf0);
                    mma_f16(a2[mt][1], qf[mt][kk], bf1);
                }
            }
#pragma unroll
            for (int mt = 0; mt < 2; mt++) {
#pragma unroll
                for (int sub = 0; sub < 2; sub++) {
                    int nt = 2 * t + sub;
                    uint32_t b0 = ((const uint32_t*)&mw[2 * mt])[nt >> 2] >> (8 * (nt & 3) + bsh);
                    uint32_t b1 = ((const uint32_t*)&mw[2 * mt + 1])[nt >> 2] >> (8 * (nt & 3) + bsh);
                    if (!(b0 & 1)) sums[2 * mt] += __expf(a2[mt][sub][0] * 0.125f);
                    if (!(b0 & 2)) sums[2 * mt] += __expf(a2[mt][sub][1] * 0.125f);
                    if (!(b1 & 1)) sums[2 * mt + 1] += __expf(a2[mt][sub][2] * 0.125f);
                    if (!(b1 & 2)) sums[2 * mt + 1] += __expf(a2[mt][sub][3] * 0.125f);
                }
            }
        }
        __syncthreads();
        if (it + 2 < 16) K1_ISSUE(it + 2);
        CP_COMMIT();
    }

#pragma unroll
    for (int r = 0; r < 4; r++) {
        sums[r] += __shfl_xor_sync(0xffffffffu, sums[r], 1);
        sums[r] += __shfl_xor_sync(0xffffffffu, sums[r], 2);
    }
    if ((lane & 3) == 0) {
#pragma unroll
        for (int r = 0; r < 4; r++)
            g_rl[(size_t)bh * SS + qg + 8 * r] = sums[r];
    }
}

// ---------------------------------------------------------------------------
// Flash pass 2: fused per-16col tile: QK mma -> exp/mask -> attn write (stream)
// -> PV mma. 128 q rows/block, 8 warps of 16 q.
// ---------------------------------------------------------------------------
#define QT_BYTES (128 * FL_ST * 2)          // 18432
#define VT_ST 136
#define VT_BYTES (64 * VT_ST * 2)           // 17408
#define P2_SMEM (QT_BYTES + 2 * KT_BYTES + 2 * VT_BYTES)  // 90112

__global__ __launch_bounds__(256, 2) void pass2_kernel(float* __restrict__ attn)
{
    int tid = threadIdx.x, wid = tid >> 5, lane = tid & 31;
    int g = lane >> 2, tig = lane & 3;
    int q0 = blockIdx.x * 128, bh = blockIdx.y;
    int b = bh >> 4, h = bh & 15;
    uint32_t sb = smem_u32(dynsm);

    {
        const __half* s = g_qh + (size_t)(b * SS + q0 + (tid >> 1)) * DD + h * 64 + (tid & 1) * 32;
        uint32_t d = sb + ((tid >> 1) * FL_ST + (tid & 1) * 32) * 2;
#pragma unroll
        for (int j = 0; j < 4; j++) CP_ASYNC16(d + j * 16, s + j * 8);
    }
    int krow = tid >> 1, kch = (tid & 1) * 32;
    const __half* srcK = g_kh + (size_t)(b * SS + krow) * DD + h * 64 + kch;
    uint32_t dstK = sb + QT_BYTES + (krow * FL_ST + kch) * 2;
    int vrow = tid >> 2, vch = (tid & 3) * 32;
    const __half* srcV = g_vth + (size_t)bh * DKK * SS + (size_t)vrow * SS + vch;
    uint32_t dstV = sb + QT_BYTES + 2 * KT_BYTES + (vrow * VT_ST + vch) * 2;

#define KV_ISSUE(st) do {                                                  \
        uint32_t soK_ = ((st) & 1) * KT_BYTES;                             \
        uint32_t soV_ = ((st) & 1) * VT_BYTES;                             \
        const __half* sk_ = srcK + (size_t)(st) * 128 * DD;                \
        const __half* sv_ = srcV + (st) * 128;                             \
        _Pragma("unroll")                                                  \
        for (int j_ = 0; j_ < 4; j_++) {                                   \
            CP_ASYNC16(dstK + soK_ + j_ * 16, sk_ + j_ * 8);               \
            CP_ASYNC16(dstV + soV_ + j_ * 16, sv_ + j_ * 8);               \
        }                                                                  \
    } while (0)

    KV_ISSUE(0); CP_COMMIT();
    KV_ISSUE(1); CP_COMMIT();

    uint32_t qoff = ((16 * wid + (lane & 15)) * FL_ST) * 2 + (lane >> 4) * 16;
    uint32_t koff = ((lane & 15) * FL_ST) * 2 + (lane >> 4) * 16;
    uint32_t voff = ((lane & 15) * VT_ST) * 2 + (lane >> 4) * 16;

    int qg = q0 + 16 * wid + g;
    const uint32_t* mb0 = g_mb + (size_t)(b * SS + qg) * 64;
    const uint32_t* mb1 = mb0 + 8 * 64;
    int bsh = 2 * tig;
    float* arow0 = attn + ((size_t)bh * SS + qg) * SS;
    float* arow1 = arow0 + 8 * (size_t)SS;
    float il0 = 1.0f / g_rl[(size_t)bh * SS + qg];
    float il1 = 1.0f / g_rl[(size_t)bh * SS + qg + 8];

    uint32_t qf[4][4];
    float o[8][4] = {};

    for (int it = 0; it < 16; ++it) {
        CP_WAIT(1);
        __syncthreads();
        if (it == 0) {
#pragma unroll
            for (int kk = 0; kk < 4; kk++)
                ldsm_x4(qf[kk], sb + qoff + kk * 32);
        }
        uint32_t soK = QT_BYTES + (it & 1) * KT_BYTES;
        uint32_t soV = QT_BYTES + 2 * KT_BYTES + (it & 1) * VT_BYTES;

        uint4 mw0 = *(const uint4*)&mb0[it * 4];
        uint4 mw1 = *(const uint4*)&mb1[it * 4];
        const uint32_t* w0 = (const uint32_t*)&mw0;
        const uint32_t* w1 = (const uint32_t*)&mw1;

#pragma unroll
        for (int t = 0; t < 8; t++) {
            float a2[2][4] = {};
#pragma unroll
            for (int kk = 0; kk < 4; kk++) {
                uint32_t bb[4];
                ldsm_x4(bb, sb + soK + koff + (16 * t * FL_ST) * 2 + kk * 32);
                uint32_t bf0[2] = { bb[0], bb[2] };
                uint32_t bf1[2] = { bb[1], bb[3] };
                mma_f16(a2[0], qf[kk], bf0);
                mma_f16(a2[1], qf[kk], bf1);
            }
            uint32_t ph[2][2];
#pragma unroll
            for (int sub = 0; sub < 2; sub++) {
                int nt = 2 * t + sub;
                int c = 8 * nt + bsh;
                uint32_t a0 = w0[nt >> 2] >> (8 * (nt & 3) + bsh);
                uint32_t a1 = w1[nt >> 2] >> (8 * (nt & 3) + bsh);
                float p0 = (a0 & 1) ? 0.f : __expf(a2[sub][0] * 0.125f) * il0;
                float p1 = (a0 & 2) ? 0.f : __expf(a2[sub][1] * 0.125f) * il0;
                float p2 = (a1 & 1) ? 0.f : __expf(a2[sub][2] * 0.125f) * il1;
                float p3 = (a1 & 2) ? 0.f : __expf(a2[sub][3] * 0.125f) * il1;
                __stcs((float2*)&arow0[it * 128 + c], make_float2(p0, p1));
                __stcs((float2*)&arow1[it * 128 + c], make_float2(p2, p3));
                ph[sub][0] = pack_h2(p0, p1);
                ph[sub][1] = pack_h2(p2, p3);
            }
            uint32_t pa[4] = { ph[0][0], ph[0][1], ph[1][0], ph[1][1] };
#pragma unroll
            for (int vt = 0; vt < 4; vt++) {
                uint32_t bb[4];
                ldsm_x4(bb, sb + soV + voff + (16 * vt * VT_ST) * 2 + t * 32);
                uint32_t bf0[2] = { bb[0], bb[2] };
                uint32_t bf1[2] = { bb[1], bb[3] };
                mma_f16(o[2 * vt], pa, bf0);
                mma_f16(o[2 * vt + 1], pa, bf1);
            }
        }
        __syncthreads();
        if (it + 2 < 16) KV_ISSUE(it + 2);
        CP_COMMIT();
    }

    int r0 = (b << 11) + qg;
#pragma unroll
    for (int nt = 0; nt < 8; nt++) {
        int c = h * 64 + 8 * nt + 2 * tig;
        *(float2*)&g_o[(size_t)r0 * DD + c] = make_float2(o[nt][0], o[nt][1]);
        *(float2*)&g_o[(size_t)(r0 + 8) * DD + c] = make_float2(o[nt][2], o[nt][3]);
    }
}

// ---------------------------------------------------------------------------
// residual + LayerNorm. One block per (b,s) row.
// ---------------------------------------------------------------------------
__global__ __launch_bounds__(256) void ln_kernel(
    const float* __restrict__ query, const float* __restrict__ gamma,
    const float* __restrict__ beta, float* __restrict__ out)
{
    __shared__ float rs[256];
    __shared__ float rs2[256];
    int rowi = blockIdx.x;
    int tid = threadIdx.x;
    size_t base = (size_t)rowi * DD;

    float4 o = __ldcs((const float4*)&g_o[base + tid * 4]);
    float4 qv = *(const float4*)&query[base + tid * 4];
    float r0 = o.x + qv.x, r1 = o.y + qv.y, r2 = o.z + qv.z, r3 = o.w + qv.w;

    rs[tid] = r0 + r1 + r2 + r3;
    rs2[tid] = r0 * r0 + r1 * r1 + r2 * r2 + r3 * r3;
    __syncthreads();
    for (int s2 = 128; s2 > 0; s2 >>= 1) {
        if (tid < s2) { rs[tid] += rs[tid + s2]; rs2[tid] += rs2[tid + s2]; }
        __syncthreads();
    }
    float mean = rs[0] * (1.0f / DD);
    float var = rs2[0] * (1.0f / DD) - mean * mean;
    float rstd = rsqrtf(var + 1e-5f);

    float4 g = *(const float4*)&gamma[tid * 4];
    float4 bt = *(const float4*)&beta[tid * 4];
    float4 res;
    res.x = (r0 - mean) * rstd * g.x + bt.x;
    res.y = (r1 - mean) * rstd * g.y + bt.y;
    res.z = (r2 - mean) * rstd * g.z + bt.z;
    res.w = (r3 - mean) * rstd * g.w + bt.w;
    *(float4*)&out[base + tid * 4] = res;
}

// ---------------------------------------------------------------------------
extern "C" void kernel_launch(void* const* d_in, const int* in_sizes, int n_in,
                              void* d_out, int out_size)
{
    (void)in_sizes; (void)n_in; (void)out_size;
    const float* key   = (const float*)d_in[0];
    const float* value = (const float*)d_in[1];
    const float* query = (const float*)d_in[2];
    const unsigned char* mask = (const unsigned char*)d_in[3];
    const float* Wq = (const float*)d_in[4];
    const float* Wk = (const float*)d_in[5];
    const float* Wv = (const float*)d_in[6];
    const float* gamma = (const float*)d_in[7];
    const float* beta  = (const float*)d_in[8];

    float* out  = (float*)d_out;                       // normed [B,S,D]
    float* attn = out + (size_t)BB * SS * DD;          // attn [B*H,S,S]

    static int attr_done = 0;
    if (!attr_done) {
        cudaFuncSetAttribute(proj_f16, cudaFuncAttributeMaxDynamicSharedMemorySize, PJ_SMEM);
        cudaFuncSetAttribute(pass1_kernel, cudaFuncAttributeMaxDynamicSharedMemorySize, P1_SMEM);
        cudaFuncSetAttribute(pass2_kernel, cudaFuncAttributeMaxDynamicSharedMemorySize, P2_SMEM);
        attr_done = 1;
    }

    maskpack_kernel<<<dim3(BB * SS * 64 / 256), 256>>>(mask);
    cvt_kernel<<<dim3(BB * SS * DD / (256 * 8), 3), 256>>>(query, key, value);
    wt_kernel<<<dim3(32, 32, 3), 256>>>(Wq, Wk, Wv);
    proj_f16<<<dim3(8, 32, 3), 256, PJ_SMEM>>>();
    pass1_kernel<<<dim3(8, 32), 256, P1_SMEM>>>();
    pass2_kernel<<<dim3(16, 32), 256, P2_SMEM>>>(attn);
    ln_kernel<<<dim3(BB * SS), 256>>>(query, gamma, beta, out);
}

// round 15
// speedup vs baseline: 1.0287x; 1.0287x over previous
#include <cuda_runtime.h>
#include <cuda_fp16.h>
#include <math.h>
#include <stdint.h>

#define BB 2
#define SS 2048
#define DD 1024
#define HH 16
#define DKK 64

// ---------------------------------------------------------------------------
// Scratch
// ---------------------------------------------------------------------------
static __device__ __half h_x[3][BB * SS * DD];     // converted inputs q,k,v
static __device__ __half h_wt[3][DD * DD];         // W^T [n][k] half
static __device__ __half g_qh[BB * SS * DD];       // Q proj [token][D]
static __device__ __half g_kh[BB * SS * DD];       // K proj [token][D]
static __device__ __half g_vth[BB * HH * DKK * SS];// V^T [B,H,DK,S]
static __device__ float  g_rl[BB * HH * SS];       // softmax row sums
static __device__ float  g_o[BB * SS * DD];        // attention out (f32)
static __device__ uint32_t g_mb[BB * SS * (SS / 32)]; // packed mask bits

// ---------------------------------------------------------------------------
// helpers
// ---------------------------------------------------------------------------
__device__ __forceinline__ uint32_t smem_u32(const void* p) {
    uint32_t a;
    asm("{ .reg .u64 t; cvta.to.shared.u64 t, %1; cvt.u32.u64 %0, t; }"
        : "=r"(a) : "l"(p));
    return a;
}
__device__ __forceinline__ void mma_f16(float* d, const uint32_t* a, const uint32_t* b) {
    asm volatile(
        "mma.sync.aligned.m16n8k16.row.col.f32.f16.f16.f32 "
        "{%0,%1,%2,%3}, {%4,%5,%6,%7}, {%8,%9}, {%0,%1,%2,%3};"
        : "+f"(d[0]), "+f"(d[1]), "+f"(d[2]), "+f"(d[3])
        : "r"(a[0]), "r"(a[1]), "r"(a[2]), "r"(a[3]), "r"(b[0]), "r"(b[1]));
}
__device__ __forceinline__ void ldsm_x4(uint32_t* r, uint32_t addr) {
    asm volatile("ldmatrix.sync.aligned.m8n8.x4.shared.b16 {%0,%1,%2,%3}, [%4];"
        : "=r"(r[0]), "=r"(r[1]), "=r"(r[2]), "=r"(r[3]) : "r"(addr));
}
__device__ __forceinline__ uint32_t pack_h2(float a, float b) {
    __half2 h = __floats2half2_rn(a, b);
    return *(uint32_t*)&h;
}
#define CP_ASYNC16(smem, gptr) \
    asm volatile("cp.async.ca.shared.global [%0], [%1], 16;" :: "r"(smem), "l"(gptr))
#define CP_COMMIT() asm volatile("cp.async.commit_group;" ::: "memory")
#define CP_WAIT(n)  asm volatile("cp.async.wait_group %0;" :: "n"(n) : "memory")

extern __shared__ uint32_t dynsm[];

// ---------------------------------------------------------------------------
// Pack mask bytes -> bits
// ---------------------------------------------------------------------------
__global__ __launch_bounds__(256) void maskpack_kernel(const unsigned char* __restrict__ mask)
{
    int idx = blockIdx.x * 256 + threadIdx.x;
    const uint32_t* src = (const uint32_t*)(mask + (size_t)idx * 32);
    uint32_t bits = 0;
#pragma unroll
    for (int i = 0; i < 8; i++) {
        uint32_t w = src[i];
#pragma unroll
        for (int j = 0; j < 4; j++)
            if ((w >> (8 * j)) & 0xFF) bits |= 1u << (4 * i + j);
    }
    g_mb[idx] = bits;
}

// ---------------------------------------------------------------------------
// Convert inputs f32 -> half
// ---------------------------------------------------------------------------
__global__ __launch_bounds__(256) void cvt_kernel(
    const float* __restrict__ q, const float* __restrict__ k, const float* __restrict__ v)
{
    int z = blockIdx.y;
    const float* src = (z == 0) ? q : (z == 1) ? k : v;
    __half* dst = h_x[z];
    size_t i = ((size_t)blockIdx.x * 256 + threadIdx.x) * 8;
    float4 a = *(const float4*)&src[i];
    float4 b = *(const float4*)&src[i + 4];
    uint4 o;
    o.x = pack_h2(a.x, a.y); o.y = pack_h2(a.z, a.w);
    o.z = pack_h2(b.x, b.y); o.w = pack_h2(b.z, b.w);
    *(uint4*)&dst[i] = o;
}

// ---------------------------------------------------------------------------
// W transpose -> half
// ---------------------------------------------------------------------------
__global__ __launch_bounds__(256) void wt_kernel(
    const float* __restrict__ Wq, const float* __restrict__ Wk, const float* __restrict__ Wv)
{
    __shared__ float t[32][33];
    int z = blockIdx.z;
    const float* W = (z == 0) ? Wq : (z == 1) ? Wk : Wv;
    __half* O = h_wt[z];
    int x0 = blockIdx.x * 32, y0 = blockIdx.y * 32;
    int tx = threadIdx.x & 31, ty = threadIdx.x >> 5;
#pragma unroll
    for (int i = 0; i < 4; i++)
        t[ty + 8 * i][tx] = W[(size_t)(y0 + ty + 8 * i) * DD + x0 + tx];
    __syncthreads();
#pragma unroll
    for (int i = 0; i < 4; i++)
        O[(size_t)(x0 + ty + 8 * i) * DD + y0 + tx] = __float2half_rn(t[tx][ty + 8 * i]);
}

// ---------------------------------------------------------------------------
// Projections (fp16): block 128m x 128n, BK=32, 3-stage cp.async pipeline,
// 8 warps (4m x 2n), warp 32x64, 2 blocks/SM.
// ---------------------------------------------------------------------------
#define PJ_ST 40
#define PJ_STAGEH ((128 + 128) * PJ_ST)     // halves per stage
#define PJ_SMEM (3 * PJ_STAGEH * 2)         // 61440 bytes

__global__ __launch_bounds__(256, 2) void proj_f16()
{
    int tid = threadIdx.x, wid = tid >> 5, lane = tid & 31;
    int z = blockIdx.z;
    const __half* X = h_x[z];
    const __half* WT = h_wt[z];
    int m0 = blockIdx.y * 128, n0 = blockIdx.x * 128;
    uint32_t sb = smem_u32(dynsm);

    int arow = tid >> 1, ach = (tid & 1) * 16;
    const __half* srcA = X + (size_t)(m0 + arow) * DD + ach;
    uint32_t dstA = sb + (arow * PJ_ST + ach) * 2;
    const __half* srcB = WT + (size_t)(n0 + arow) * DD + ach;
    uint32_t dstB = sb + ((128 + arow) * PJ_ST + ach) * 2;

#define PJF_ISSUE(st) do {                                                 \
        uint32_t so_ = ((st) % 3) * (PJ_STAGEH * 2);                       \
        const __half* a_ = srcA + (st) * 32;                               \
        const __half* b_ = srcB + (st) * 32;                               \
        CP_ASYNC16(dstA + so_, a_);                                        \
        CP_ASYNC16(dstA + so_ + 16, a_ + 8);                               \
        CP_ASYNC16(dstB + so_, b_);                                        \
        CP_ASYNC16(dstB + so_ + 16, b_ + 8);                               \
    } while (0)

    PJF_ISSUE(0); CP_COMMIT();
    PJF_ISSUE(1); CP_COMMIT();
    PJF_ISSUE(2); CP_COMMIT();

    int wm = (wid & 3) * 32, wn = (wid >> 2) * 64;
    uint32_t aoff0 = ((wm + (lane & 15)) * PJ_ST) * 2 + (lane >> 4) * 16;
    uint32_t aoff1 = ((wm + 16 + (lane & 15)) * PJ_ST) * 2 + (lane >> 4) * 16;
    uint32_t boff = ((128 + wn + (lane & 15)) * PJ_ST) * 2 + (lane >> 4) * 16;

    float acc[2][8][4] = {};

    for (int it = 0; it < 32; ++it) {
        CP_WAIT(2);
        __syncthreads();
        uint32_t so = (it % 3) * (PJ_STAGEH * 2);
#pragma unroll
        for (int ks = 0; ks < 2; ks++) {
            uint32_t af[2][4];
            ldsm_x4(af[0], sb + so + aoff0 + ks * 32);
            ldsm_x4(af[1], sb + so + aoff1 + ks * 32);
#pragma unroll
            for (int t = 0; t < 4; t++) {
                uint32_t bb[4];
                ldsm_x4(bb, sb + so + boff + (16 * t * PJ_ST) * 2 + ks * 32);
                uint32_t bf0[2] = { bb[0], bb[2] };
                uint32_t bf1[2] = { bb[1], bb[3] };
#pragma unroll
                for (int i = 0; i < 2; i++) {
                    mma_f16(acc[i][2 * t], af[i], bf0);
                    mma_f16(acc[i][2 * t + 1], af[i], bf1);
                }
            }
        }
        __syncthreads();
        if (it + 3 < 32) PJF_ISSUE(it + 3);
        CP_COMMIT();
    }

    int g = lane >> 2, tig = lane & 3;
    if (z < 2) {
        __half* O = (z == 0) ? g_qh : g_kh;
#pragma unroll
        for (int i = 0; i < 2; i++) {
            int r0 = m0 + wm + 16 * i + g;
#pragma unroll
            for (int j = 0; j < 8; j++) {
                int c = n0 + wn + 8 * j + 2 * tig;
                *(uint32_t*)&O[(size_t)r0 * DD + c] = pack_h2(acc[i][j][0], acc[i][j][1]);
                *(uint32_t*)&O[(size_t)(r0 + 8) * DD + c] = pack_h2(acc[i][j][2], acc[i][j][3]);
            }
        }
    } else {
        int h = (n0 + wn) >> 6;
#pragma unroll
        for (int i = 0; i < 2; i++) {
            int r0 = m0 + wm + 16 * i + g;
#pragma unroll
            for (int j = 0; j < 8; j++) {
                int dk = 8 * j + 2 * tig;
#pragma unroll
                for (int e = 0; e < 4; e++) {
                    int gm = r0 + (e >> 1) * 8;
                    int b = gm >> 11, s = gm & 2047;
                    g_vth[(((size_t)(b * HH + h)) * DKK + dk + (e & 1)) * SS + s] =
                        __float2half_rn(acc[i][j][e]);
                }
            }
        }
    }
}

// ---------------------------------------------------------------------------
// Flash pass 1: row sums l = sum_k e^{s/8}. 256 q rows/block, 8 warps of 32 q.
// ---------------------------------------------------------------------------
#define FL_ST 72
#define QT1_BYTES (256 * FL_ST * 2)         // 36864
#define KT_BYTES (128 * FL_ST * 2)          // 18432
#define P1_SMEM (QT1_BYTES + 2 * KT_BYTES)  // 73728

__global__ __launch_bounds__(256) void pass1_kernel()
{
    int tid = threadIdx.x, wid = tid >> 5, lane = tid & 31;
    int g = lane >> 2, tig = lane & 3;
    int q0 = blockIdx.x * 256, bh = blockIdx.y;
    int b = bh >> 4, h = bh & 15;
    uint32_t sb = smem_u32(dynsm);

    {   // Q fill: one row per thread — full 64 halves = 8 x 16B
        const __half* s = g_qh + (size_t)(b * SS + q0 + tid) * DD + h * 64;
        uint32_t d = sb + (tid * FL_ST) * 2;
#pragma unroll
        for (int j = 0; j < 8; j++) CP_ASYNC16(d + j * 16, s + j * 8);
    }
    int krow = tid >> 1, kch = (tid & 1) * 32;
    const __half* srcK = g_kh + (size_t)(b * SS + krow) * DD + h * 64 + kch;
    uint32_t dstK = sb + QT1_BYTES + (krow * FL_ST + kch) * 2;

#define K1_ISSUE(st) do {                                                  \
        uint32_t so_ = ((st) & 1) * KT_BYTES;                              \
        const __half* s_ = srcK + (size_t)(st) * 128 * DD;                 \
        _Pragma("unroll")                                                  \
        for (int j_ = 0; j_ < 4; j_++)                                     \
            CP_ASYNC16(dstK + so_ + j_ * 16, s_ + j_ * 8);                 \
    } while (0)

    K1_ISSUE(0); CP_COMMIT();
    K1_ISSUE(1); CP_COMMIT();

    uint32_t qoff0 = ((32 * wid + (lane & 15)) * FL_ST) * 2 + (lane >> 4) * 16;
    uint32_t qoff1 = ((32 * wid + 16 + (lane & 15)) * FL_ST) * 2 + (lane >> 4) * 16;
    uint32_t koff = ((lane & 15) * FL_ST) * 2 + (lane >> 4) * 16;

    int qg = q0 + 32 * wid + g;
    const uint32_t* mbp[4];
#pragma unroll
    for (int r = 0; r < 4; r++)
        mbp[r] = g_mb + (size_t)(b * SS + qg + 8 * r) * 64;
    int bsh = 2 * tig;

    uint32_t qf[2][4][4];
    float sums[4] = { 0.f, 0.f, 0.f, 0.f };

    for (int it = 0; it < 16; ++it) {
        CP_WAIT(1);
        __syncthreads();
        if (it == 0) {
#pragma unroll
            for (int kk = 0; kk < 4; kk++) {
                ldsm_x4(qf[0][kk], sb + qoff0 + kk * 32);
                ldsm_x4(qf[1][kk], sb + qoff1 + kk * 32);
            }
        }
        uint32_t so = QT1_BYTES + (it & 1) * KT_BYTES;
        uint4 mw[4];
#pragma unroll
        for (int r = 0; r < 4; r++) mw[r] = *(const uint4*)&mbp[r][it * 4];

#pragma unroll
        for (int t = 0; t < 8; t++) {
            float a2[2][2][4] = {};
#pragma unroll
            for (int kk = 0; kk < 4; kk++) {
                uint32_t bb[4];
                ldsm_x4(bb, sb + so + koff + (16 * t * FL_ST) * 2 + kk * 32);
                uint32_t bf0[2] = { bb[0], bb[2] };
                uint32_t bf1[2] = { bb[1], bb[3] };
#pragma unroll
                for (int mt = 0; mt < 2; mt++) {
                    mma_f16(a2[mt][0], qf[mt][kk], bf0);
                    mma_f16(a2[mt][1], qf[mt][kk], bf1);
                }
            }
#pragma unroll
            for (int mt = 0; mt < 2; mt++) {
#pragma unroll
                for (int sub = 0; sub < 2; sub++) {
                    int nt = 2 * t + sub;
                    uint32_t b0 = ((const uint32_t*)&mw[2 * mt])[nt >> 2] >> (8 * (nt & 3) + bsh);
                    uint32_t b1 = ((const uint32_t*)&mw[2 * mt + 1])[nt >> 2] >> (8 * (nt & 3) + bsh);
                    if (!(b0 & 1)) sums[2 * mt] += __expf(a2[mt][sub][0] * 0.125f);
                    if (!(b0 & 2)) sums[2 * mt] += __expf(a2[mt][sub][1] * 0.125f);
                    if (!(b1 & 1)) sums[2 * mt + 1] += __expf(a2[mt][sub][2] * 0.125f);
                    if (!(b1 & 2)) sums[2 * mt + 1] += __expf(a2[mt][sub][3] * 0.125f);
                }
            }
        }
        __syncthreads();
        if (it + 2 < 16) K1_ISSUE(it + 2);
        CP_COMMIT();
    }

#pragma unroll
    for (int r = 0; r < 4; r++) {
        sums[r] += __shfl_xor_sync(0xffffffffu, sums[r], 1);
        sums[r] += __shfl_xor_sync(0xffffffffu, sums[r], 2);
    }
    if ((lane & 3) == 0) {
#pragma unroll
        for (int r = 0; r < 4; r++)
            g_rl[(size_t)bh * SS + qg + 8 * r] = sums[r];
    }
}

// ---------------------------------------------------------------------------
// Flash pass 2: fused per-16col tile: QK mma -> exp/mask -> attn write -> PV mma.
// 128 q rows/block, 8 warps of 16 q.
// ---------------------------------------------------------------------------
#define QT_BYTES (128 * FL_ST * 2)          // 18432
#define VT_ST 136
#define VT_BYTES (64 * VT_ST * 2)           // 17408
#define P2_SMEM (QT_BYTES + 2 * KT_BYTES + 2 * VT_BYTES)  // 90112

__global__ __launch_bounds__(256) void pass2_kernel(float* __restrict__ attn)
{
    int tid = threadIdx.x, wid = tid >> 5, lane = tid & 31;
    int g = lane >> 2, tig = lane & 3;
    int q0 = blockIdx.x * 128, bh = blockIdx.y;
    int b = bh >> 4, h = bh & 15;
    uint32_t sb = smem_u32(dynsm);

    {
        const __half* s = g_qh + (size_t)(b * SS + q0 + (tid >> 1)) * DD + h * 64 + (tid & 1) * 32;
        uint32_t d = sb + ((tid >> 1) * FL_ST + (tid & 1) * 32) * 2;
#pragma unroll
        for (int j = 0; j < 4; j++) CP_ASYNC16(d + j * 16, s + j * 8);
    }
    int krow = tid >> 1, kch = (tid & 1) * 32;
    const __half* srcK = g_kh + (size_t)(b * SS + krow) * DD + h * 64 + kch;
    uint32_t dstK = sb + QT_BYTES + (krow * FL_ST + kch) * 2;
    int vrow = tid >> 2, vch = (tid & 3) * 32;
    const __half* srcV = g_vth + (size_t)bh * DKK * SS + (size_t)vrow * SS + vch;
    uint32_t dstV = sb + QT_BYTES + 2 * KT_BYTES + (vrow * VT_ST + vch) * 2;

#define KV_ISSUE(st) do {                                                  \
        uint32_t soK_ = ((st) & 1) * KT_BYTES;                             \
        uint32_t soV_ = ((st) & 1) * VT_BYTES;                             \
        const __half* sk_ = srcK + (size_t)(st) * 128 * DD;                \
        const __half* sv_ = srcV + (st) * 128;                             \
        _Pragma("unroll")                                                  \
        for (int j_ = 0; j_ < 4; j_++) {                                   \
            CP_ASYNC16(dstK + soK_ + j_ * 16, sk_ + j_ * 8);               \
            CP_ASYNC16(dstV + soV_ + j_ * 16, sv_ + j_ * 8);               \
        }                                                                  \
    } while (0)

    KV_ISSUE(0); CP_COMMIT();
    KV_ISSUE(1); CP_COMMIT();

    uint32_t qoff = ((16 * wid + (lane & 15)) * FL_ST) * 2 + (lane >> 4) * 16;
    uint32_t koff = ((lane & 15) * FL_ST) * 2 + (lane >> 4) * 16;
    uint32_t voff = ((lane & 15) * VT_ST) * 2 + (lane >> 4) * 16;

    int qg = q0 + 16 * wid + g;
    const uint32_t* mb0 = g_mb + (size_t)(b * SS + qg) * 64;
    const uint32_t* mb1 = mb0 + 8 * 64;
    int bsh = 2 * tig;
    float* arow0 = attn + ((size_t)bh * SS + qg) * SS;
    float* arow1 = arow0 + 8 * (size_t)SS;
    float il0 = 1.0f / g_rl[(size_t)bh * SS + qg];
    float il1 = 1.0f / g_rl[(size_t)bh * SS + qg + 8];

    uint32_t qf[4][4];
    float o[8][4] = {};

    for (int it = 0; it < 16; ++it) {
        CP_WAIT(1);
        __syncthreads();
        if (it == 0) {
#pragma unroll
            for (int kk = 0; kk < 4; kk++)
                ldsm_x4(qf[kk], sb + qoff + kk * 32);
        }
        uint32_t soK = QT_BYTES + (it & 1) * KT_BYTES;
        uint32_t soV = QT_BYTES + 2 * KT_BYTES + (it & 1) * VT_BYTES;

        uint4 mw0 = *(const uint4*)&mb0[it * 4];
        uint4 mw1 = *(const uint4*)&mb1[it * 4];
        const uint32_t* w0 = (const uint32_t*)&mw0;
        const uint32_t* w1 = (const uint32_t*)&mw1;

#pragma unroll
        for (int t = 0; t < 8; t++) {
            float a2[2][4] = {};
#pragma unroll
            for (int kk = 0; kk < 4; kk++) {
                uint32_t bb[4];
                ldsm_x4(bb, sb + soK + koff + (16 * t * FL_ST) * 2 + kk * 32);
                uint32_t bf0[2] = { bb[0], bb[2] };
                uint32_t bf1[2] = { bb[1], bb[3] };
                mma_f16(a2[0], qf[kk], bf0);
                mma_f16(a2[1], qf[kk], bf1);
            }
            uint32_t ph[2][2];
#pragma unroll
            for (int sub = 0; sub < 2; sub++) {
                int nt = 2 * t + sub;
                int c = 8 * nt + bsh;
                uint32_t a0 = w0[nt >> 2] >> (8 * (nt & 3) + bsh);
                uint32_t a1 = w1[nt >> 2] >> (8 * (nt & 3) + bsh);
                float p0 = (a0 & 1) ? 0.f : __expf(a2[sub][0] * 0.125f) * il0;
                float p1 = (a0 & 2) ? 0.f : __expf(a2[sub][1] * 0.125f) * il0;
                float p2 = (a1 & 1) ? 0.f : __expf(a2[sub][2] * 0.125f) * il1;
                float p3 = (a1 & 2) ? 0.f : __expf(a2[sub][3] * 0.125f) * il1;
                *(float2*)&arow0[it * 128 + c] = make_float2(p0, p1);
                *(float2*)&arow1[it * 128 + c] = make_float2(p2, p3);
                ph[sub][0] = pack_h2(p0, p1);
                ph[sub][1] = pack_h2(p2, p3);
            }
            uint32_t pa[4] = { ph[0][0], ph[0][1], ph[1][0], ph[1][1] };
#pragma unroll
            for (int vt = 0; vt < 4; vt++) {
                uint32_t bb[4];
                ldsm_x4(bb, sb + soV + voff + (16 * vt * VT_ST) * 2 + t * 32);
                uint32_t bf0[2] = { bb[0], bb[2] };
                uint32_t bf1[2] = { bb[1], bb[3] };
                mma_f16(o[2 * vt], pa, bf0);
                mma_f16(o[2 * vt + 1], pa, bf1);
            }
        }
        __syncthreads();
        if (it + 2 < 16) KV_ISSUE(it + 2);
        CP_COMMIT();
    }

    int r0 = (b << 11) + qg;
#pragma unroll
    for (int nt = 0; nt < 8; nt++) {
        int c = h * 64 + 8 * nt + 2 * tig;
        *(float2*)&g_o[(size_t)r0 * DD + c] = make_float2(o[nt][0], o[nt][1]);
        *(float2*)&g_o[(size_t)(r0 + 8) * DD + c] = make_float2(o[nt][2], o[nt][3]);
    }
}

// ---------------------------------------------------------------------------
// residual + LayerNorm. One block per (b,s) row.
// ---------------------------------------------------------------------------
__global__ __launch_bounds__(256) void ln_kernel(
    const float* __restrict__ query, const float* __restrict__ gamma,
    const float* __restrict__ beta, float* __restrict__ out)
{
    __shared__ float rs[256];
    __shared__ float rs2[256];
    int rowi = blockIdx.x;
    int tid = threadIdx.x;
    size_t base = (size_t)rowi * DD;

    float4 o = *(const float4*)&g_o[base + tid * 4];
    float4 qv = *(const float4*)&query[base + tid * 4];
    float r0 = o.x + qv.x, r1 = o.y + qv.y, r2 = o.z + qv.z, r3 = o.w + qv.w;

    rs[tid] = r0 + r1 + r2 + r3;
    rs2[tid] = r0 * r0 + r1 * r1 + r2 * r2 + r3 * r3;
    __syncthreads();
    for (int s2 = 128; s2 > 0; s2 >>= 1) {
        if (tid < s2) { rs[tid] += rs[tid + s2]; rs2[tid] += rs2[tid + s2]; }
        __syncthreads();
    }
    float mean = rs[0] * (1.0f / DD);
    float var = rs2[0] * (1.0f / DD) - mean * mean;
    float rstd = rsqrtf(var + 1e-5f);

    float4 g = *(const float4*)&gamma[tid * 4];
    float4 bt = *(const float4*)&beta[tid * 4];
    float4 res;
    res.x = (r0 - mean) * rstd * g.x + bt.x;
    res.y = (r1 - mean) * rstd * g.y + bt.y;
    res.z = (r2 - mean) * rstd * g.z + bt.z;
    res.w = (r3 - mean) * rstd * g.w + bt.w;
    *(float4*)&out[base + tid * 4] = res;
}

// ---------------------------------------------------------------------------
extern "C" void kernel_launch(void* const* d_in, const int* in_sizes, int n_in,
                              void* d_out, int out_size)
{
    (void)in_sizes; (void)n_in; (void)out_size;
    const float* key   = (const float*)d_in[0];
    const float* value = (const float*)d_in[1];
    const float* query = (const float*)d_in[2];
    const unsigned char* mask = (const unsigned char*)d_in[3];
    const float* Wq = (const float*)d_in[4];
    const float* Wk = (const float*)d_in[5];
    const float* Wv = (const float*)d_in[6];
    const float* gamma = (const float*)d_in[7];
    const float* beta  = (const float*)d_in[8];

    float* out  = (float*)d_out;                       // normed [B,S,D]
    float* attn = out + (size_t)BB * SS * DD;          // attn [B*H,S,S]

    static int attr_done = 0;
    if (!attr_done) {
        cudaFuncSetAttribute(proj_f16, cudaFuncAttributeMaxDynamicSharedMemorySize, PJ_SMEM);
        cudaFuncSetAttribute(pass1_kernel, cudaFuncAttributeMaxDynamicSharedMemorySize, P1_SMEM);
        cudaFuncSetAttribute(pass2_kernel, cudaFuncAttributeMaxDynamicSharedMemorySize, P2_SMEM);
        attr_done = 1;
    }

    maskpack_kernel<<<dim3(BB * SS * 64 / 256), 256>>>(mask);
    cvt_kernel<<<dim3(BB * SS * DD / (256 * 8), 3), 256>>>(query, key, value);
    wt_kernel<<<dim3(32, 32, 3), 256>>>(Wq, Wk, Wv);
    proj_f16<<<dim3(8, 32, 3), 256, PJ_SMEM>>>();
    pass1_kernel<<<dim3(8, 32), 256, P1_SMEM>>>();
    pass2_kernel<<<dim3(16, 32), 256, P2_SMEM>>>(attn);
    ln_kernel<<<dim3(BB * SS), 256>>>(query, gamma, beta, out);
}

// round 16
// speedup vs baseline: 1.0450x; 1.0158x over previous
#include <cuda_runtime.h>
#include <cuda_fp16.h>
#include <math.h>
#include <stdint.h>

#define BB 2
#define SS 2048
#define DD 1024
#define HH 16
#define DKK 64

// ---------------------------------------------------------------------------
// Scratch
// ---------------------------------------------------------------------------
static __device__ __half h_x[3][BB * SS * DD];     // converted inputs q,k,v
static __device__ __half h_wt[3][DD * DD];         // W^T [n][k] half
static __device__ __half g_qh[BB * SS * DD];       // Q proj [token][D]
static __device__ __half g_kh[BB * SS * DD];       // K proj [token][D]
static __device__ __half g_vth[BB * HH * DKK * SS];// V^T [B,H,DK,S]
static __device__ float  g_rl[BB * HH * SS];       // softmax row sums
static __device__ float  g_o[BB * SS * DD];        // attention out (f32)
static __device__ uint32_t g_mb[BB * SS * (SS / 32)]; // packed mask bits

// ---------------------------------------------------------------------------
// helpers
// ---------------------------------------------------------------------------
__device__ __forceinline__ uint32_t smem_u32(const void* p) {
    uint32_t a;
    asm("{ .reg .u64 t; cvta.to.shared.u64 t, %1; cvt.u32.u64 %0, t; }"
        : "=r"(a) : "l"(p));
    return a;
}
__device__ __forceinline__ void mma_f16(float* d, const uint32_t* a, const uint32_t* b) {
    asm volatile(
        "mma.sync.aligned.m16n8k16.row.col.f32.f16.f16.f32 "
        "{%0,%1,%2,%3}, {%4,%5,%6,%7}, {%8,%9}, {%0,%1,%2,%3};"
        : "+f"(d[0]), "+f"(d[1]), "+f"(d[2]), "+f"(d[3])
        : "r"(a[0]), "r"(a[1]), "r"(a[2]), "r"(a[3]), "r"(b[0]), "r"(b[1]));
}
__device__ __forceinline__ void ldsm_x4(uint32_t* r, uint32_t addr) {
    asm volatile("ldmatrix.sync.aligned.m8n8.x4.shared.b16 {%0,%1,%2,%3}, [%4];"
        : "=r"(r[0]), "=r"(r[1]), "=r"(r[2]), "=r"(r[3]) : "r"(addr));
}
__device__ __forceinline__ uint32_t pack_h2(float a, float b) {
    __half2 h = __floats2half2_rn(a, b);
    return *(uint32_t*)&h;
}
#define CP_ASYNC16(smem, gptr) \
    asm volatile("cp.async.ca.shared.global [%0], [%1], 16;" :: "r"(smem), "l"(gptr))
#define CP_COMMIT() asm volatile("cp.async.commit_group;" ::: "memory")
#define CP_WAIT(n)  asm volatile("cp.async.wait_group %0;" :: "n"(n) : "memory")

extern __shared__ uint32_t dynsm[];

// ---------------------------------------------------------------------------
// Pack mask bytes -> bits
// ---------------------------------------------------------------------------
__global__ __launch_bounds__(256) void maskpack_kernel(const unsigned char* __restrict__ mask)
{
    int idx = blockIdx.x * 256 + threadIdx.x;
    const uint32_t* src = (const uint32_t*)(mask + (size_t)idx * 32);
    uint32_t bits = 0;
#pragma unroll
    for (int i = 0; i < 8; i++) {
        uint32_t w = src[i];
#pragma unroll
        for (int j = 0; j < 4; j++)
            if ((w >> (8 * j)) & 0xFF) bits |= 1u << (4 * i + j);
    }
    g_mb[idx] = bits;
}

// ---------------------------------------------------------------------------
// Convert inputs f32 -> half
// ---------------------------------------------------------------------------
__global__ __launch_bounds__(256) void cvt_kernel(
    const float* __restrict__ q, const float* __restrict__ k, const float* __restrict__ v)
{
    int z = blockIdx.y;
    const float* src = (z == 0) ? q : (z == 1) ? k : v;
    __half* dst = h_x[z];
    size_t i = ((size_t)blockIdx.x * 256 + threadIdx.x) * 8;
    float4 a = *(const float4*)&src[i];
    float4 b = *(const float4*)&src[i + 4];
    uint4 o;
    o.x = pack_h2(a.x, a.y); o.y = pack_h2(a.z, a.w);
    o.z = pack_h2(b.x, b.y); o.w = pack_h2(b.z, b.w);
    *(uint4*)&dst[i] = o;
}

// ---------------------------------------------------------------------------
// W transpose -> half
// ---------------------------------------------------------------------------
__global__ __launch_bounds__(256) void wt_kernel(
    const float* __restrict__ Wq, const float* __restrict__ Wk, const float* __restrict__ Wv)
{
    __shared__ float t[32][33];
    int z = blockIdx.z;
    const float* W = (z == 0) ? Wq : (z == 1) ? Wk : Wv;
    __half* O = h_wt[z];
    int x0 = blockIdx.x * 32, y0 = blockIdx.y * 32;
    int tx = threadIdx.x & 31, ty = threadIdx.x >> 5;
#pragma unroll
    for (int i = 0; i < 4; i++)
        t[ty + 8 * i][tx] = W[(size_t)(y0 + ty + 8 * i) * DD + x0 + tx];
    __syncthreads();
#pragma unroll
    for (int i = 0; i < 4; i++)
        O[(size_t)(x0 + ty + 8 * i) * DD + y0 + tx] = __float2half_rn(t[tx][ty + 8 * i]);
}

// ---------------------------------------------------------------------------
// Projections (fp16): block 128m x 128n, BK=32, 2-stage, 8 warps (4m x 2n),
// warp 32x64, 2 blocks/SM.   (R13 configuration — best measured)
// ---------------------------------------------------------------------------
#define PJ_ST 40
#define PJ_STAGEH ((128 + 128) * PJ_ST)     // halves per stage
#define PJ_SMEM (2 * PJ_STAGEH * 2)         // 40960 bytes

__global__ __launch_bounds__(256, 2) void proj_f16()
{
    int tid = threadIdx.x, wid = tid >> 5, lane = tid & 31;
    int z = blockIdx.z;
    const __half* X = h_x[z];
    const __half* WT = h_wt[z];
    int m0 = blockIdx.y * 128, n0 = blockIdx.x * 128;
    uint32_t sb = smem_u32(dynsm);

    int arow = tid >> 1, ach = (tid & 1) * 16;
    const __half* srcA = X + (size_t)(m0 + arow) * DD + ach;
    uint32_t dstA = sb + (arow * PJ_ST + ach) * 2;
    const __half* srcB = WT + (size_t)(n0 + arow) * DD + ach;
    uint32_t dstB = sb + ((128 + arow) * PJ_ST + ach) * 2;

#define PJF_ISSUE(st) do {                                                 \
        uint32_t so_ = ((st) & 1) * (PJ_STAGEH * 2);                       \
        const __half* a_ = srcA + (st) * 32;                               \
        const __half* b_ = srcB + (st) * 32;                               \
        CP_ASYNC16(dstA + so_, a_);                                        \
        CP_ASYNC16(dstA + so_ + 16, a_ + 8);                               \
        CP_ASYNC16(dstB + so_, b_);                                        \
        CP_ASYNC16(dstB + so_ + 16, b_ + 8);                               \
    } while (0)

    PJF_ISSUE(0); CP_COMMIT();
    PJF_ISSUE(1); CP_COMMIT();

    int wm = (wid & 3) * 32, wn = (wid >> 2) * 64;
    uint32_t aoff0 = ((wm + (lane & 15)) * PJ_ST) * 2 + (lane >> 4) * 16;
    uint32_t aoff1 = ((wm + 16 + (lane & 15)) * PJ_ST) * 2 + (lane >> 4) * 16;
    uint32_t boff = ((128 + wn + (lane & 15)) * PJ_ST) * 2 + (lane >> 4) * 16;

    float acc[2][8][4] = {};

    for (int it = 0; it < 32; ++it) {
        CP_WAIT(1);
        __syncthreads();
        uint32_t so = (it & 1) * (PJ_STAGEH * 2);
#pragma unroll
        for (int ks = 0; ks < 2; ks++) {
            uint32_t af[2][4];
            ldsm_x4(af[0], sb + so + aoff0 + ks * 32);
            ldsm_x4(af[1], sb + so + aoff1 + ks * 32);
#pragma unroll
            for (int t = 0; t < 4; t++) {
                uint32_t bb[4];
                ldsm_x4(bb, sb + so + boff + (16 * t * PJ_ST) * 2 + ks * 32);
                uint32_t bf0[2] = { bb[0], bb[2] };
                uint32_t bf1[2] = { bb[1], bb[3] };
#pragma unroll
                for (int i = 0; i < 2; i++) {
                    mma_f16(acc[i][2 * t], af[i], bf0);
                    mma_f16(acc[i][2 * t + 1], af[i], bf1);
                }
            }
        }
        __syncthreads();
        if (it + 2 < 32) PJF_ISSUE(it + 2);
        CP_COMMIT();
    }

    int g = lane >> 2, tig = lane & 3;
    if (z < 2) {
        __half* O = (z == 0) ? g_qh : g_kh;
#pragma unroll
        for (int i = 0; i < 2; i++) {
            int r0 = m0 + wm + 16 * i + g;
#pragma unroll
            for (int j = 0; j < 8; j++) {
                int c = n0 + wn + 8 * j + 2 * tig;
                *(uint32_t*)&O[(size_t)r0 * DD + c] = pack_h2(acc[i][j][0], acc[i][j][1]);
                *(uint32_t*)&O[(size_t)(r0 + 8) * DD + c] = pack_h2(acc[i][j][2], acc[i][j][3]);
            }
        }
    } else {
        int h = (n0 + wn) >> 6;
#pragma unroll
        for (int i = 0; i < 2; i++) {
            int r0 = m0 + wm + 16 * i + g;
#pragma unroll
            for (int j = 0; j < 8; j++) {
                int dk = 8 * j + 2 * tig;
#pragma unroll
                for (int e = 0; e < 4; e++) {
                    int gm = r0 + (e >> 1) * 8;
                    int b = gm >> 11, s = gm & 2047;
                    g_vth[(((size_t)(b * HH + h)) * DKK + dk + (e & 1)) * SS + s] =
                        __float2half_rn(acc[i][j][e]);
                }
            }
        }
    }
}

// ---------------------------------------------------------------------------
// Flash pass 1: row sums l = sum_k e^{s/8}. 256 q rows/block, 8 warps of 32 q.
// ---------------------------------------------------------------------------
#define FL_ST 72
#define QT1_BYTES (256 * FL_ST * 2)         // 36864
#define KT_BYTES (128 * FL_ST * 2)          // 18432
#define P1_SMEM (QT1_BYTES + 2 * KT_BYTES)  // 73728

__global__ __launch_bounds__(256) void pass1_kernel()
{
    int tid = threadIdx.x, wid = tid >> 5, lane = tid & 31;
    int g = lane >> 2, tig = lane & 3;
    int q0 = blockIdx.x * 256, bh = blockIdx.y;
    int b = bh >> 4, h = bh & 15;
    uint32_t sb = smem_u32(dynsm);

    {   // Q fill: one row per thread — full 64 halves = 8 x 16B
        const __half* s = g_qh + (size_t)(b * SS + q0 + tid) * DD + h * 64;
        uint32_t d = sb + (tid * FL_ST) * 2;
#pragma unroll
        for (int j = 0; j < 8; j++) CP_ASYNC16(d + j * 16, s + j * 8);
    }
    int krow = tid >> 1, kch = (tid & 1) * 32;
    const __half* srcK = g_kh + (size_t)(b * SS + krow) * DD + h * 64 + kch;
    uint32_t dstK = sb + QT1_BYTES + (krow * FL_ST + kch) * 2;

#define K1_ISSUE(st) do {                                                  \
        uint32_t so_ = ((st) & 1) * KT_BYTES;                              \
        const __half* s_ = srcK + (size_t)(st) * 128 * DD;                 \
        _Pragma("unroll")                                                  \
        for (int j_ = 0; j_ < 4; j_++)                                     \
            CP_ASYNC16(dstK + so_ + j_ * 16, s_ + j_ * 8);                 \
    } while (0)

    K1_ISSUE(0); CP_COMMIT();
    K1_ISSUE(1); CP_COMMIT();

    uint32_t qoff0 = ((32 * wid + (lane & 15)) * FL_ST) * 2 + (lane >> 4) * 16;
    uint32_t qoff1 = ((32 * wid + 16 + (lane & 15)) * FL_ST) * 2 + (lane >> 4) * 16;
    uint32_t koff = ((lane & 15) * FL_ST) * 2 + (lane >> 4) * 16;

    int qg = q0 + 32 * wid + g;
    const uint32_t* mbp[4];
#pragma unroll
    for (int r = 0; r < 4; r++)
        mbp[r] = g_mb + (size_t)(b * SS + qg + 8 * r) * 64;
    int bsh = 2 * tig;

    uint32_t qf[2][4][4];
    float sums[4] = { 0.f, 0.f, 0.f, 0.f };

    for (int it = 0; it < 16; ++it) {
        CP_WAIT(1);
        __syncthreads();
        if (it == 0) {
#pragma unroll
            for (int kk = 0; kk < 4; kk++) {
                ldsm_x4(qf[0][kk], sb + qoff0 + kk * 32);
                ldsm_x4(qf[1][kk], sb + qoff1 + kk * 32);
            }
        }
        uint32_t so = QT1_BYTES + (it & 1) * KT_BYTES;
        uint4 mw[4];
#pragma unroll
        for (int r = 0; r < 4; r++) mw[r] = *(const uint4*)&mbp[r][it * 4];

#pragma unroll
        for (int t = 0; t < 8; t++) {
            float a2[2][2][4] = {};
#pragma unroll
            for (int kk = 0; kk < 4; kk++) {
                uint32_t bb[4];
                ldsm_x4(bb, sb + so + koff + (16 * t * FL_ST) * 2 + kk * 32);
                uint32_t bf0[2] = { bb[0], bb[2] };
                uint32_t bf1[2] = { bb[1], bb[3] };
#pragma unroll
                for (int mt = 0; mt < 2; mt++) {
                    mma_f16(a2[mt][0], qf[mt][kk], bf0);
                    mma_f16(a2[mt][1], qf[mt][kk], bf1);
                }
            }
#pragma unroll
            for (int mt = 0; mt < 2; mt++) {
#pragma unroll
                for (int sub = 0; sub < 2; sub++) {
                    int nt = 2 * t + sub;
                    uint32_t b0 = ((const uint32_t*)&mw[2 * mt])[nt >> 2] >> (8 * (nt & 3) + bsh);
                    uint32_t b1 = ((const uint32_t*)&mw[2 * mt + 1])[nt >> 2] >> (8 * (nt & 3) + bsh);
                    if (!(b0 & 1)) sums[2 * mt] += __expf(a2[mt][sub][0] * 0.125f);
                    if (!(b0 & 2)) sums[2 * mt] += __expf(a2[mt][sub][1] * 0.125f);
                    if (!(b1 & 1)) sums[2 * mt + 1] += __expf(a2[mt][sub][2] * 0.125f);
                    if (!(b1 & 2)) sums[2 * mt + 1] += __expf(a2[mt][sub][3] * 0.125f);
                }
            }
        }
        __syncthreads();
        if (it + 2 < 16) K1_ISSUE(it + 2);
        CP_COMMIT();
    }

#pragma unroll
    for (int r = 0; r < 4; r++) {
        sums[r] += __shfl_xor_sync(0xffffffffu, sums[r], 1);
        sums[r] += __shfl_xor_sync(0xffffffffu, sums[r], 2);
    }
    if ((lane & 3) == 0) {
#pragma unroll
        for (int r = 0; r < 4; r++)
            g_rl[(size_t)bh * SS + qg + 8 * r] = sums[r];
    }
}

// ---------------------------------------------------------------------------
// Flash pass 2: fused per-16col tile: QK mma -> exp/mask -> attn write -> PV mma.
// 128 q rows/block, 8 warps of 16 q.
// ---------------------------------------------------------------------------
#define QT_BYTES (128 * FL_ST * 2)          // 18432
#define VT_ST 136
#define VT_BYTES (64 * VT_ST * 2)           // 17408
#define P2_SMEM (QT_BYTES + 2 * KT_BYTES + 2 * VT_BYTES)  // 90112

__global__ __launch_bounds__(256) void pass2_kernel(float* __restrict__ attn)
{
    int tid = threadIdx.x, wid = tid >> 5, lane = tid & 31;
    int g = lane >> 2, tig = lane & 3;
    int q0 = blockIdx.x * 128, bh = blockIdx.y;
    int b = bh >> 4, h = bh & 15;
    uint32_t sb = smem_u32(dynsm);

    {
        const __half* s = g_qh + (size_t)(b * SS + q0 + (tid >> 1)) * DD + h * 64 + (tid & 1) * 32;
        uint32_t d = sb + ((tid >> 1) * FL_ST + (tid & 1) * 32) * 2;
#pragma unroll
        for (int j = 0; j < 4; j++) CP_ASYNC16(d + j * 16, s + j * 8);
    }
    int krow = tid >> 1, kch = (tid & 1) * 32;
    const __half* srcK = g_kh + (size_t)(b * SS + krow) * DD + h * 64 + kch;
    uint32_t dstK = sb + QT_BYTES + (krow * FL_ST + kch) * 2;
    int vrow = tid >> 2, vch = (tid & 3) * 32;
    const __half* srcV = g_vth + (size_t)bh * DKK * SS + (size_t)vrow * SS + vch;
    uint32_t dstV = sb + QT_BYTES + 2 * KT_BYTES + (vrow * VT_ST + vch) * 2;

#define KV_ISSUE(st) do {                                                  \
        uint32_t soK_ = ((st) & 1) * KT_BYTES;                             \
        uint32_t soV_ = ((st) & 1) * VT_BYTES;                             \
        const __half* sk_ = srcK + (size_t)(st) * 128 * DD;                \
        const __half* sv_ = srcV + (st) * 128;                             \
        _Pragma("unroll")                                                  \
        for (int j_ = 0; j_ < 4; j_++) {                                   \
            CP_ASYNC16(dstK + soK_ + j_ * 16, sk_ + j_ * 8);               \
            CP_ASYNC16(dstV + soV_ + j_ * 16, sv_ + j_ * 8);               \
        }                                                                  \
    } while (0)

    KV_ISSUE(0); CP_COMMIT();
    KV_ISSUE(1); CP_COMMIT();

    uint32_t qoff = ((16 * wid + (lane & 15)) * FL_ST) * 2 + (lane >> 4) * 16;
    uint32_t koff = ((lane & 15) * FL_ST) * 2 + (lane >> 4) * 16;
    uint32_t voff = ((lane & 15) * VT_ST) * 2 + (lane >> 4) * 16;

    int qg = q0 + 16 * wid + g;
    const uint32_t* mb0 = g_mb + (size_t)(b * SS + qg) * 64;
    const uint32_t* mb1 = mb0 + 8 * 64;
    int bsh = 2 * tig;
    float* arow0 = attn + ((size_t)bh * SS + qg) * SS;
    float* arow1 = arow0 + 8 * (size_t)SS;
    float il0 = 1.0f / g_rl[(size_t)bh * SS + qg];
    float il1 = 1.0f / g_rl[(size_t)bh * SS + qg + 8];

    uint32_t qf[4][4];
    float o[8][4] = {};

    for (int it = 0; it < 16; ++it) {
        CP_WAIT(1);
        __syncthreads();
        if (it == 0) {
#pragma unroll
            for (int kk = 0; kk < 4; kk++)
                ldsm_x4(qf[kk], sb + qoff + kk * 32);
        }
        uint32_t soK = QT_BYTES + (it & 1) * KT_BYTES;
        uint32_t soV = QT_BYTES + 2 * KT_BYTES + (it & 1) * VT_BYTES;

        uint4 mw0 = *(const uint4*)&mb0[it * 4];
        uint4 mw1 = *(const uint4*)&mb1[it * 4];
        const uint32_t* w0 = (const uint32_t*)&mw0;
        const uint32_t* w1 = (const uint32_t*)&mw1;

#pragma unroll
        for (int t = 0; t < 8; t++) {
            float a2[2][4] = {};
#pragma unroll
            for (int kk = 0; kk < 4; kk++) {
                uint32_t bb[4];
                ldsm_x4(bb, sb + soK + koff + (16 * t * FL_ST) * 2 + kk * 32);
                uint32_t bf0[2] = { bb[0], bb[2] };
                uint32_t bf1[2] = { bb[1], bb[3] };
                mma_f16(a2[0], qf[kk], bf0);
                mma_f16(a2[1], qf[kk], bf1);
            }
            uint32_t ph[2][2];
#pragma unroll
            for (int sub = 0; sub < 2; sub++) {
                int nt = 2 * t + sub;
                int c = 8 * nt + bsh;
                uint32_t a0 = w0[nt >> 2] >> (8 * (nt & 3) + bsh);
                uint32_t a1 = w1[nt >> 2] >> (8 * (nt & 3) + bsh);
                float p0 = (a0 & 1) ? 0.f : __expf(a2[sub][0] * 0.125f) * il0;
                float p1 = (a0 & 2) ? 0.f : __expf(a2[sub][1] * 0.125f) * il0;
                float p2 = (a1 & 1) ? 0.f : __expf(a2[sub][2] * 0.125f) * il1;
                float p3 = (a1 & 2) ? 0.f : __expf(a2[sub][3] * 0.125f) * il1;
                *(float2*)&arow0[it * 128 + c] = make_float2(p0, p1);
                *(float2*)&arow1[it * 128 + c] = make_float2(p2, p3);
                ph[sub][0] = pack_h2(p0, p1);
                ph[sub][1] = pack_h2(p2, p3);
            }
            uint32_t pa[4] = { ph[0][0], ph[0][1], ph[1][0], ph[1][1] };
#pragma unroll
            for (int vt = 0; vt < 4; vt++) {
                uint32_t bb[4];
                ldsm_x4(bb, sb + soV + voff + (16 * vt * VT_ST) * 2 + t * 32);
                uint32_t bf0[2] = { bb[0], bb[2] };
                uint32_t bf1[2] = { bb[1], bb[3] };
                mma_f16(o[2 * vt], pa, bf0);
                mma_f16(o[2 * vt + 1], pa, bf1);
            }
        }
        __syncthreads();
        if (it + 2 < 16) KV_ISSUE(it + 2);
        CP_COMMIT();
    }

    int r0 = (b << 11) + qg;
#pragma unroll
    for (int nt = 0; nt < 8; nt++) {
        int c = h * 64 + 8 * nt + 2 * tig;
        *(float2*)&g_o[(size_t)r0 * DD + c] = make_float2(o[nt][0], o[nt][1]);
        *(float2*)&g_o[(size_t)(r0 + 8) * DD + c] = make_float2(o[nt][2], o[nt][3]);
    }
}

// ---------------------------------------------------------------------------
// residual + LayerNorm. One block per (b,s) row — warp-shuffle reduction.
// ---------------------------------------------------------------------------
__global__ __launch_bounds__(256) void ln_kernel(
    const float* __restrict__ query, const float* __restrict__ gamma,
    const float* __restrict__ beta, float* __restrict__ out)
{
    __shared__ float ws[8], ws2[8];
    int rowi = blockIdx.x;
    int tid = threadIdx.x, lane = tid & 31, wid = tid >> 5;
    size_t base = (size_t)rowi * DD;

    float4 o = *(const float4*)&g_o[base + tid * 4];
    float4 qv = *(const float4*)&query[base + tid * 4];
    float r0 = o.x + qv.x, r1 = o.y + qv.y, r2 = o.z + qv.z, r3 = o.w + qv.w;

    float s = r0 + r1 + r2 + r3;
    float s2 = r0 * r0 + r1 * r1 + r2 * r2 + r3 * r3;
#pragma unroll
    for (int d = 16; d > 0; d >>= 1) {
        s += __shfl_xor_sync(0xffffffffu, s, d);
        s2 += __shfl_xor_sync(0xffffffffu, s2, d);
    }
    if (lane == 0) { ws[wid] = s; ws2[wid] = s2; }
    __syncthreads();
    if (wid == 0) {
        float a = (lane < 8) ? ws[lane] : 0.f;
        float b = (lane < 8) ? ws2[lane] : 0.f;
#pragma unroll
        for (int d = 4; d > 0; d >>= 1) {
            a += __shfl_xor_sync(0xffffffffu, a, d);
            b += __shfl_xor_sync(0xffffffffu, b, d);
        }
        if (lane == 0) { ws[0] = a; ws2[0] = b; }
    }
    __syncthreads();

    float mean = ws[0] * (1.0f / DD);
    float var = ws2[0] * (1.0f / DD) - mean * mean;
    float rstd = rsqrtf(var + 1e-5f);

    float4 g = *(const float4*)&gamma[tid * 4];
    float4 bt = *(const float4*)&beta[tid * 4];
    float4 res;
    res.x = (r0 - mean) * rstd * g.x + bt.x;
    res.y = (r1 - mean) * rstd * g.y + bt.y;
    res.z = (r2 - mean) * rstd * g.z + bt.z;
    res.w = (r3 - mean) * rstd * g.w + bt.w;
    *(float4*)&out[base + tid * 4] = res;
}

// ---------------------------------------------------------------------------
extern "C" void kernel_launch(void* const* d_in, const int* in_sizes, int n_in,
                              void* d_out, int out_size)
{
    (void)in_sizes; (void)n_in; (void)out_size;
    const float* key   = (const float*)d_in[0];
    const float* value = (const float*)d_in[1];
    const float* query = (const float*)d_in[2];
    const unsigned char* mask = (const unsigned char*)d_in[3];
    const float* Wq = (const float*)d_in[4];
    const float* Wk = (const float*)d_in[5];
    const float* Wv = (const float*)d_in[6];
    const float* gamma = (const float*)d_in[7];
    const float* beta  = (const float*)d_in[8];

    float* out  = (float*)d_out;                       // normed [B,S,D]
    float* attn = out + (size_t)BB * SS * DD;          // attn [B*H,S,S]

    static int attr_done = 0;
    if (!attr_done) {
        cudaFuncSetAttribute(proj_f16, cudaFuncAttributeMaxDynamicSharedMemorySize, PJ_SMEM);
        cudaFuncSetAttribute(pass1_kernel, cudaFuncAttributeMaxDynamicSharedMemorySize, P1_SMEM);
        cudaFuncSetAttribute(pass2_kernel, cudaFuncAttributeMaxDynamicSharedMemorySize, P2_SMEM);
        attr_done = 1;
    }

    maskpack_kernel<<<dim3(BB * SS * 64 / 256), 256>>>(mask);
    cvt_kernel<<<dim3(BB * SS * DD / (256 * 8), 3), 256>>>(query, key, value);
    wt_kernel<<<dim3(32, 32, 3), 256>>>(Wq, Wk, Wv);
    proj_f16<<<dim3(8, 32, 3), 256, PJ_SMEM>>>();
    pass1_kernel<<<dim3(8, 32), 256, P1_SMEM>>>();
    pass2_kernel<<<dim3(16, 32), 256, P2_SMEM>>>(attn);
    ln_kernel<<<dim3(BB * SS), 256>>>(query, gamma, beta, out);
}

// round 17
// speedup vs baseline: 1.0528x; 1.0075x over previous
#include <cuda_runtime.h>
#include <cuda_fp16.h>
#include <math.h>
#include <stdint.h>

#define BB 2
#define SS 2048
#define DD 1024
#define HH 16
#define DKK 64

// ---------------------------------------------------------------------------
// Scratch
// ---------------------------------------------------------------------------
static __device__ __half h_x[3][BB * SS * DD];     // converted inputs q,k,v
static __device__ __half h_wt[3][DD * DD];         // W^T [n][k] half
static __device__ __half g_qh[BB * SS * DD];       // Q proj [token][D]
static __device__ __half g_kh[BB * SS * DD];       // K proj [token][D]
static __device__ __half g_vth[BB * HH * DKK * SS];// V^T [B,H,DK,S]
static __device__ float  g_rl[BB * HH * SS];       // softmax row sums
static __device__ float  g_o[BB * SS * DD];        // attention out (f32)
static __device__ uint32_t g_mb[BB * SS * (SS / 32)]; // packed mask bits

// ---------------------------------------------------------------------------
// helpers
// ---------------------------------------------------------------------------
__device__ __forceinline__ uint32_t smem_u32(const void* p) {
    uint32_t a;
    asm("{ .reg .u64 t; cvta.to.shared.u64 t, %1; cvt.u32.u64 %0, t; }"
        : "=r"(a) : "l"(p));
    return a;
}
__device__ __forceinline__ void mma_f16(float* d, const uint32_t* a, const uint32_t* b) {
    asm volatile(
        "mma.sync.aligned.m16n8k16.row.col.f32.f16.f16.f32 "
        "{%0,%1,%2,%3}, {%4,%5,%6,%7}, {%8,%9}, {%0,%1,%2,%3};"
        : "+f"(d[0]), "+f"(d[1]), "+f"(d[2]), "+f"(d[3])
        : "r"(a[0]), "r"(a[1]), "r"(a[2]), "r"(a[3]), "r"(b[0]), "r"(b[1]));
}
__device__ __forceinline__ void ldsm_x4(uint32_t* r, uint32_t addr) {
    asm volatile("ldmatrix.sync.aligned.m8n8.x4.shared.b16 {%0,%1,%2,%3}, [%4];"
        : "=r"(r[0]), "=r"(r[1]), "=r"(r[2]), "=r"(r[3]) : "r"(addr));
}
__device__ __forceinline__ uint32_t pack_h2(float a, float b) {
    __half2 h = __floats2half2_rn(a, b);
    return *(uint32_t*)&h;
}
#define CP_ASYNC16(smem, gptr) \
    asm volatile("cp.async.ca.shared.global [%0], [%1], 16;" :: "r"(smem), "l"(gptr))
#define CP_COMMIT() asm volatile("cp.async.commit_group;" ::: "memory")
#define CP_WAIT(n)  asm volatile("cp.async.wait_group %0;" :: "n"(n) : "memory")

extern __shared__ uint32_t dynsm[];

// ---------------------------------------------------------------------------
// Pack mask bytes -> bits
// ---------------------------------------------------------------------------
__global__ __launch_bounds__(256) void maskpack_kernel(const unsigned char* __restrict__ mask)
{
    int idx = blockIdx.x * 256 + threadIdx.x;
    const uint32_t* src = (const uint32_t*)(mask + (size_t)idx * 32);
    uint32_t bits = 0;
#pragma unroll
    for (int i = 0; i < 8; i++) {
        uint32_t w = src[i];
#pragma unroll
        for (int j = 0; j < 4; j++)
            if ((w >> (8 * j)) & 0xFF) bits |= 1u << (4 * i + j);
    }
    g_mb[idx] = bits;
}

// ---------------------------------------------------------------------------
// Convert inputs f32 -> half   (z = z0 + blockIdx.y)
// ---------------------------------------------------------------------------
__global__ __launch_bounds__(256) void cvt_kernel(
    int z0, const float* __restrict__ q, const float* __restrict__ k,
    const float* __restrict__ v)
{
    int z = z0 + blockIdx.y;
    const float* src = (z == 0) ? q : (z == 1) ? k : v;
    __half* dst = h_x[z];
    size_t i = ((size_t)blockIdx.x * 256 + threadIdx.x) * 8;
    float4 a = *(const float4*)&src[i];
    float4 b = *(const float4*)&src[i + 4];
    uint4 o;
    o.x = pack_h2(a.x, a.y); o.y = pack_h2(a.z, a.w);
    o.z = pack_h2(b.x, b.y); o.w = pack_h2(b.z, b.w);
    *(uint4*)&dst[i] = o;
}

// ---------------------------------------------------------------------------
// W transpose -> half   (z = z0 + blockIdx.z)
// ---------------------------------------------------------------------------
__global__ __launch_bounds__(256) void wt_kernel(
    int z0, const float* __restrict__ Wq, const float* __restrict__ Wk,
    const float* __restrict__ Wv)
{
    __shared__ float t[32][33];
    int z = z0 + blockIdx.z;
    const float* W = (z == 0) ? Wq : (z == 1) ? Wk : Wv;
    __half* O = h_wt[z];
    int x0 = blockIdx.x * 32, y0 = blockIdx.y * 32;
    int tx = threadIdx.x & 31, ty = threadIdx.x >> 5;
#pragma unroll
    for (int i = 0; i < 4; i++)
        t[ty + 8 * i][tx] = W[(size_t)(y0 + ty + 8 * i) * DD + x0 + tx];
    __syncthreads();
#pragma unroll
    for (int i = 0; i < 4; i++)
        O[(size_t)(x0 + ty + 8 * i) * DD + y0 + tx] = __float2half_rn(t[tx][ty + 8 * i]);
}

// ---------------------------------------------------------------------------
// Projections (fp16): block 128m x 128n, BK=32, 2-stage, 8 warps (4m x 2n),
// warp 32x64, 2 blocks/SM.   (z = z0 + blockIdx.z)
// ---------------------------------------------------------------------------
#define PJ_ST 40
#define PJ_STAGEH ((128 + 128) * PJ_ST)     // halves per stage
#define PJ_SMEM (2 * PJ_STAGEH * 2)         // 40960 bytes

__global__ __launch_bounds__(256, 2) void proj_f16(int z0)
{
    int tid = threadIdx.x, wid = tid >> 5, lane = tid & 31;
    int z = z0 + blockIdx.z;
    const __half* X = h_x[z];
    const __half* WT = h_wt[z];
    int m0 = blockIdx.y * 128, n0 = blockIdx.x * 128;
    uint32_t sb = smem_u32(dynsm);

    int arow = tid >> 1, ach = (tid & 1) * 16;
    const __half* srcA = X + (size_t)(m0 + arow) * DD + ach;
    uint32_t dstA = sb + (arow * PJ_ST + ach) * 2;
    const __half* srcB = WT + (size_t)(n0 + arow) * DD + ach;
    uint32_t dstB = sb + ((128 + arow) * PJ_ST + ach) * 2;

#define PJF_ISSUE(st) do {                                                 \
        uint32_t so_ = ((st) & 1) * (PJ_STAGEH * 2);                       \
        const __half* a_ = srcA + (st) * 32;                               \
        const __half* b_ = srcB + (st) * 32;                               \
        CP_ASYNC16(dstA + so_, a_);                                        \
        CP_ASYNC16(dstA + so_ + 16, a_ + 8);                               \
        CP_ASYNC16(dstB + so_, b_);                                        \
        CP_ASYNC16(dstB + so_ + 16, b_ + 8);                               \
    } while (0)

    PJF_ISSUE(0); CP_COMMIT();
    PJF_ISSUE(1); CP_COMMIT();

    int wm = (wid & 3) * 32, wn = (wid >> 2) * 64;
    uint32_t aoff0 = ((wm + (lane & 15)) * PJ_ST) * 2 + (lane >> 4) * 16;
    uint32_t aoff1 = ((wm + 16 + (lane & 15)) * PJ_ST) * 2 + (lane >> 4) * 16;
    uint32_t boff = ((128 + wn + (lane & 15)) * PJ_ST) * 2 + (lane >> 4) * 16;

    float acc[2][8][4] = {};

    for (int it = 0; it < 32; ++it) {
        CP_WAIT(1);
        __syncthreads();
        uint32_t so = (it & 1) * (PJ_STAGEH * 2);
#pragma unroll
        for (int ks = 0; ks < 2; ks++) {
            uint32_t af[2][4];
            ldsm_x4(af[0], sb + so + aoff0 + ks * 32);
            ldsm_x4(af[1], sb + so + aoff1 + ks * 32);
#pragma unroll
            for (int t = 0; t < 4; t++) {
                uint32_t bb[4];
                ldsm_x4(bb, sb + so + boff + (16 * t * PJ_ST) * 2 + ks * 32);
                uint32_t bf0[2] = { bb[0], bb[2] };
                uint32_t bf1[2] = { bb[1], bb[3] };
#pragma unroll
                for (int i = 0; i < 2; i++) {
                    mma_f16(acc[i][2 * t], af[i], bf0);
                    mma_f16(acc[i][2 * t + 1], af[i], bf1);
                }
            }
        }
        __syncthreads();
        if (it + 2 < 32) PJF_ISSUE(it + 2);
        CP_COMMIT();
    }

    int g = lane >> 2, tig = lane & 3;
    if (z < 2) {
        __half* O = (z == 0) ? g_qh : g_kh;
#pragma unroll
        for (int i = 0; i < 2; i++) {
            int r0 = m0 + wm + 16 * i + g;
#pragma unroll
            for (int j = 0; j < 8; j++) {
                int c = n0 + wn + 8 * j + 2 * tig;
                *(uint32_t*)&O[(size_t)r0 * DD + c] = pack_h2(acc[i][j][0], acc[i][j][1]);
                *(uint32_t*)&O[(size_t)(r0 + 8) * DD + c] = pack_h2(acc[i][j][2], acc[i][j][3]);
            }
        }
    } else {
        int h = (n0 + wn) >> 6;
#pragma unroll
        for (int i = 0; i < 2; i++) {
            int r0 = m0 + wm + 16 * i + g;
#pragma unroll
            for (int j = 0; j < 8; j++) {
                int dk = 8 * j + 2 * tig;
#pragma unroll
                for (int e = 0; e < 4; e++) {
                    int gm = r0 + (e >> 1) * 8;
                    int b = gm >> 11, s = gm & 2047;
                    g_vth[(((size_t)(b * HH + h)) * DKK + dk + (e & 1)) * SS + s] =
                        __float2half_rn(acc[i][j][e]);
                }
            }
        }
    }
}

// ---------------------------------------------------------------------------
// Flash pass 1: row sums l = sum_k e^{s/8}. 256 q rows/block, 8 warps of 32 q.
// ---------------------------------------------------------------------------
#define FL_ST 72
#define QT1_BYTES (256 * FL_ST * 2)         // 36864
#define KT_BYTES (128 * FL_ST * 2)          // 18432
#define P1_SMEM (QT1_BYTES + 2 * KT_BYTES)  // 73728

__global__ __launch_bounds__(256) void pass1_kernel()
{
    int tid = threadIdx.x, wid = tid >> 5, lane = tid & 31;
    int g = lane >> 2, tig = lane & 3;
    int q0 = blockIdx.x * 256, bh = blockIdx.y;
    int b = bh >> 4, h = bh & 15;
    uint32_t sb = smem_u32(dynsm);

    {   // Q fill: one row per thread — full 64 halves = 8 x 16B
        const __half* s = g_qh + (size_t)(b * SS + q0 + tid) * DD + h * 64;
        uint32_t d = sb + (tid * FL_ST) * 2;
#pragma unroll
        for (int j = 0; j < 8; j++) CP_ASYNC16(d + j * 16, s + j * 8);
    }
    int krow = tid >> 1, kch = (tid & 1) * 32;
    const __half* srcK = g_kh + (size_t)(b * SS + krow) * DD + h * 64 + kch;
    uint32_t dstK = sb + QT1_BYTES + (krow * FL_ST + kch) * 2;

#define K1_ISSUE(st) do {                                                  \
        uint32_t so_ = ((st) & 1) * KT_BYTES;                              \
        const __half* s_ = srcK + (size_t)(st) * 128 * DD;                 \
        _Pragma("unroll")                                                  \
        for (int j_ = 0; j_ < 4; j_++)                                     \
            CP_ASYNC16(dstK + so_ + j_ * 16, s_ + j_ * 8);                 \
    } while (0)

    K1_ISSUE(0); CP_COMMIT();
    K1_ISSUE(1); CP_COMMIT();

    uint32_t qoff0 = ((32 * wid + (lane & 15)) * FL_ST) * 2 + (lane >> 4) * 16;
    uint32_t qoff1 = ((32 * wid + 16 + (lane & 15)) * FL_ST) * 2 + (lane >> 4) * 16;
    uint32_t koff = ((lane & 15) * FL_ST) * 2 + (lane >> 4) * 16;

    int qg = q0 + 32 * wid + g;
    const uint32_t* mbp[4];
#pragma unroll
    for (int r = 0; r < 4; r++)
        mbp[r] = g_mb + (size_t)(b * SS + qg + 8 * r) * 64;
    int bsh = 2 * tig;

    uint32_t qf[2][4][4];
    float sums[4] = { 0.f, 0.f, 0.f, 0.f };

    for (int it = 0; it < 16; ++it) {
        CP_WAIT(1);
        __syncthreads();
        if (it == 0) {
#pragma unroll
            for (int kk = 0; kk < 4; kk++) {
                ldsm_x4(qf[0][kk], sb + qoff0 + kk * 32);
                ldsm_x4(qf[1][kk], sb + qoff1 + kk * 32);
            }
        }
        uint32_t so = QT1_BYTES + (it & 1) * KT_BYTES;
        uint4 mw[4];
#pragma unroll
        for (int r = 0; r < 4; r++) mw[r] = *(const uint4*)&mbp[r][it * 4];

#pragma unroll
        for (int t = 0; t < 8; t++) {
            float a2[2][2][4] = {};
#pragma unroll
            for (int kk = 0; kk < 4; kk++) {
                uint32_t bb[4];
                ldsm_x4(bb, sb + so + koff + (16 * t * FL_ST) * 2 + kk * 32);
                uint32_t bf0[2] = { bb[0], bb[2] };
                uint32_t bf1[2] = { bb[1], bb[3] };
#pragma unroll
                for (int mt = 0; mt < 2; mt++) {
                    mma_f16(a2[mt][0], qf[mt][kk], bf0);
                    mma_f16(a2[mt][1], qf[mt][kk], bf1);
                }
            }
#pragma unroll
            for (int mt = 0; mt < 2; mt++) {
#pragma unroll
                for (int sub = 0; sub < 2; sub++) {
                    int nt = 2 * t + sub;
                    uint32_t b0 = ((const uint32_t*)&mw[2 * mt])[nt >> 2] >> (8 * (nt & 3) + bsh);
                    uint32_t b1 = ((const uint32_t*)&mw[2 * mt + 1])[nt >> 2] >> (8 * (nt & 3) + bsh);
                    if (!(b0 & 1)) sums[2 * mt] += __expf(a2[mt][sub][0] * 0.125f);
                    if (!(b0 & 2)) sums[2 * mt] += __expf(a2[mt][sub][1] * 0.125f);
                    if (!(b1 & 1)) sums[2 * mt + 1] += __expf(a2[mt][sub][2] * 0.125f);
                    if (!(b1 & 2)) sums[2 * mt + 1] += __expf(a2[mt][sub][3] * 0.125f);
                }
            }
        }
        __syncthreads();
        if (it + 2 < 16) K1_ISSUE(it + 2);
        CP_COMMIT();
    }

#pragma unroll
    for (int r = 0; r < 4; r++) {
        sums[r] += __shfl_xor_sync(0xffffffffu, sums[r], 1);
        sums[r] += __shfl_xor_sync(0xffffffffu, sums[r], 2);
    }
    if ((lane & 3) == 0) {
#pragma unroll
        for (int r = 0; r < 4; r++)
            g_rl[(size_t)bh * SS + qg + 8 * r] = sums[r];
    }
}

// ---------------------------------------------------------------------------
// Flash pass 2: fused per-16col tile: QK mma -> exp/mask -> attn write -> PV mma.
// 128 q rows/block, 8 warps of 16 q.
// ---------------------------------------------------------------------------
#define QT_BYTES (128 * FL_ST * 2)          // 18432
#define VT_ST 136
#define VT_BYTES (64 * VT_ST * 2)           // 17408
#define P2_SMEM (QT_BYTES + 2 * KT_BYTES + 2 * VT_BYTES)  // 90112

__global__ __launch_bounds__(256) void pass2_kernel(float* __restrict__ attn)
{
    int tid = threadIdx.x, wid = tid >> 5, lane = tid & 31;
    int g = lane >> 2, tig = lane & 3;
    int q0 = blockIdx.x * 128, bh = blockIdx.y;
    int b = bh >> 4, h = bh & 15;
    uint32_t sb = smem_u32(dynsm);

    {
        const __half* s = g_qh + (size_t)(b * SS + q0 + (tid >> 1)) * DD + h * 64 + (tid & 1) * 32;
        uint32_t d = sb + ((tid >> 1) * FL_ST + (tid & 1) * 32) * 2;
#pragma unroll
        for (int j = 0; j < 4; j++) CP_ASYNC16(d + j * 16, s + j * 8);
    }
    int krow = tid >> 1, kch = (tid & 1) * 32;
    const __half* srcK = g_kh + (size_t)(b * SS + krow) * DD + h * 64 + kch;
    uint32_t dstK = sb + QT_BYTES + (krow * FL_ST + kch) * 2;
    int vrow = tid >> 2, vch = (tid & 3) * 32;
    const __half* srcV = g_vth + (size_t)bh * DKK * SS + (size_t)vrow * SS + vch;
    uint32_t dstV = sb + QT_BYTES + 2 * KT_BYTES + (vrow * VT_ST + vch) * 2;

#define KV_ISSUE(st) do {                                                  \
        uint32_t soK_ = ((st) & 1) * KT_BYTES;                             \
        uint32_t soV_ = ((st) & 1) * VT_BYTES;                             \
        const __half* sk_ = srcK + (size_t)(st) * 128 * DD;                \
        const __half* sv_ = srcV + (st) * 128;                             \
        _Pragma("unroll")                                                  \
        for (int j_ = 0; j_ < 4; j_++) {                                   \
            CP_ASYNC16(dstK + soK_ + j_ * 16, sk_ + j_ * 8);               \
            CP_ASYNC16(dstV + soV_ + j_ * 16, sv_ + j_ * 8);               \
        }                                                                  \
    } while (0)

    KV_ISSUE(0); CP_COMMIT();
    KV_ISSUE(1); CP_COMMIT();

    uint32_t qoff = ((16 * wid + (lane & 15)) * FL_ST) * 2 + (lane >> 4) * 16;
    uint32_t koff = ((lane & 15) * FL_ST) * 2 + (lane >> 4) * 16;
    uint32_t voff = ((lane & 15) * VT_ST) * 2 + (lane >> 4) * 16;

    int qg = q0 + 16 * wid + g;
    const uint32_t* mb0 = g_mb + (size_t)(b * SS + qg) * 64;
    const uint32_t* mb1 = mb0 + 8 * 64;
    int bsh = 2 * tig;
    float* arow0 = attn + ((size_t)bh * SS + qg) * SS;
    float* arow1 = arow0 + 8 * (size_t)SS;
    float il0 = 1.0f / g_rl[(size_t)bh * SS + qg];
    float il1 = 1.0f / g_rl[(size_t)bh * SS + qg + 8];

    uint32_t qf[4][4];
    float o[8][4] = {};

    for (int it = 0; it < 16; ++it) {
        CP_WAIT(1);
        __syncthreads();
        if (it == 0) {
#pragma unroll
            for (int kk = 0; kk < 4; kk++)
                ldsm_x4(qf[kk], sb + qoff + kk * 32);
        }
        uint32_t soK = QT_BYTES + (it & 1) * KT_BYTES;
        uint32_t soV = QT_BYTES + 2 * KT_BYTES + (it & 1) * VT_BYTES;

        uint4 mw0 = *(const uint4*)&mb0[it * 4];
        uint4 mw1 = *(const uint4*)&mb1[it * 4];
        const uint32_t* w0 = (const uint32_t*)&mw0;
        const uint32_t* w1 = (const uint32_t*)&mw1;

#pragma unroll
        for (int t = 0; t < 8; t++) {
            float a2[2][4] = {};
#pragma unroll
            for (int kk = 0; kk < 4; kk++) {
                uint32_t bb[4];
                ldsm_x4(bb, sb + soK + koff + (16 * t * FL_ST) * 2 + kk * 32);
                uint32_t bf0[2] = { bb[0], bb[2] };
                uint32_t bf1[2] = { bb[1], bb[3] };
                mma_f16(a2[0], qf[kk], bf0);
                mma_f16(a2[1], qf[kk], bf1);
            }
            uint32_t ph[2][2];
#pragma unroll
            for (int sub = 0; sub < 2; sub++) {
                int nt = 2 * t + sub;
                int c = 8 * nt + bsh;
                uint32_t a0 = w0[nt >> 2] >> (8 * (nt & 3) + bsh);
                uint32_t a1 = w1[nt >> 2] >> (8 * (nt & 3) + bsh);
                float p0 = (a0 & 1) ? 0.f : __expf(a2[sub][0] * 0.125f) * il0;
                float p1 = (a0 & 2) ? 0.f : __expf(a2[sub][1] * 0.125f) * il0;
                float p2 = (a1 & 1) ? 0.f : __expf(a2[sub][2] * 0.125f) * il1;
                float p3 = (a1 & 2) ? 0.f : __expf(a2[sub][3] * 0.125f) * il1;
                *(float2*)&arow0[it * 128 + c] = make_float2(p0, p1);
                *(float2*)&arow1[it * 128 + c] = make_float2(p2, p3);
                ph[sub][0] = pack_h2(p0, p1);
                ph[sub][1] = pack_h2(p2, p3);
            }
            uint32_t pa[4] = { ph[0][0], ph[0][1], ph[1][0], ph[1][1] };
#pragma unroll
            for (int vt = 0; vt < 4; vt++) {
                uint32_t bb[4];
                ldsm_x4(bb, sb + soV + voff + (16 * vt * VT_ST) * 2 + t * 32);
                uint32_t bf0[2] = { bb[0], bb[2] };
                uint32_t bf1[2] = { bb[1], bb[3] };
                mma_f16(o[2 * vt], pa, bf0);
                mma_f16(o[2 * vt + 1], pa, bf1);
            }
        }
        __syncthreads();
        if (it + 2 < 16) KV_ISSUE(it + 2);
        CP_COMMIT();
    }

    int r0 = (b << 11) + qg;
#pragma unroll
    for (int nt = 0; nt < 8; nt++) {
        int c = h * 64 + 8 * nt + 2 * tig;
        *(float2*)&g_o[(size_t)r0 * DD + c] = make_float2(o[nt][0], o[nt][1]);
        *(float2*)&g_o[(size_t)(r0 + 8) * DD + c] = make_float2(o[nt][2], o[nt][3]);
    }
}

// ---------------------------------------------------------------------------
// residual + LayerNorm. One block per (b,s) row — warp-shuffle reduction.
// ---------------------------------------------------------------------------
__global__ __launch_bounds__(256) void ln_kernel(
    const float* __restrict__ query, const float* __restrict__ gamma,
    const float* __restrict__ beta, float* __restrict__ out)
{
    __shared__ float ws[8], ws2[8];
    int rowi = blockIdx.x;
    int tid = threadIdx.x, lane = tid & 31, wid = tid >> 5;
    size_t base = (size_t)rowi * DD;

    float4 o = *(const float4*)&g_o[base + tid * 4];
    float4 qv = *(const float4*)&query[base + tid * 4];
    float r0 = o.x + qv.x, r1 = o.y + qv.y, r2 = o.z + qv.z, r3 = o.w + qv.w;

    float s = r0 + r1 + r2 + r3;
    float s2 = r0 * r0 + r1 * r1 + r2 * r2 + r3 * r3;
#pragma unroll
    for (int d = 16; d > 0; d >>= 1) {
        s += __shfl_xor_sync(0xffffffffu, s, d);
        s2 += __shfl_xor_sync(0xffffffffu, s2, d);
    }
    if (lane == 0) { ws[wid] = s; ws2[wid] = s2; }
    __syncthreads();
    if (wid == 0) {
        float a = (lane < 8) ? ws[lane] : 0.f;
        float b = (lane < 8) ? ws2[lane] : 0.f;
#pragma unroll
        for (int d = 4; d > 0; d >>= 1) {
            a += __shfl_xor_sync(0xffffffffu, a, d);
            b += __shfl_xor_sync(0xffffffffu, b, d);
        }
        if (lane == 0) { ws[0] = a; ws2[0] = b; }
    }
    __syncthreads();

    float mean = ws[0] * (1.0f / DD);
    float var = ws2[0] * (1.0f / DD) - mean * mean;
    float rstd = rsqrtf(var + 1e-5f);

    float4 g = *(const float4*)&gamma[tid * 4];
    float4 bt = *(const float4*)&beta[tid * 4];
    float4 res;
    res.x = (r0 - mean) * rstd * g.x + bt.x;
    res.y = (r1 - mean) * rstd * g.y + bt.y;
    res.z = (r2 - mean) * rstd * g.z + bt.z;
    res.w = (r3 - mean) * rstd * g.w + bt.w;
    *(float4*)&out[base + tid * 4] = res;
}

// ---------------------------------------------------------------------------
extern "C" void kernel_launch(void* const* d_in, const int* in_sizes, int n_in,
                              void* d_out, int out_size)
{
    (void)in_sizes; (void)n_in; (void)out_size;
    const float* key   = (const float*)d_in[0];
    const float* value = (const float*)d_in[1];
    const float* query = (const float*)d_in[2];
    const unsigned char* mask = (const unsigned char*)d_in[3];
    const float* Wq = (const float*)d_in[4];
    const float* Wk = (const float*)d_in[5];
    const float* Wv = (const float*)d_in[6];
    const float* gamma = (const float*)d_in[7];
    const float* beta  = (const float*)d_in[8];

    float* out  = (float*)d_out;                       // normed [B,S,D]
    float* attn = out + (size_t)BB * SS * DD;          // attn [B*H,S,S]

    static cudaStream_t sB;
    static cudaEvent_t evRoot, evB;
    static int init_done = 0;
    if (!init_done) {
        cudaFuncSetAttribute(proj_f16, cudaFuncAttributeMaxDynamicSharedMemorySize, PJ_SMEM);
        cudaFuncSetAttribute(pass1_kernel, cudaFuncAttributeMaxDynamicSharedMemorySize, P1_SMEM);
        cudaFuncSetAttribute(pass2_kernel, cudaFuncAttributeMaxDynamicSharedMemorySize, P2_SMEM);
        cudaStreamCreateWithFlags(&sB, cudaStreamNonBlocking);
        cudaEventCreateWithFlags(&evRoot, cudaEventDisableTiming);
        cudaEventCreateWithFlags(&evB, cudaEventDisableTiming);
        init_done = 1;
    }

    // Fork chain B (V path) off the main stream.
    cudaEventRecord(evRoot, 0);
    cudaStreamWaitEvent(sB, evRoot, 0);

    // Chain B: cvt(v) -> wt(v) -> proj(v)
    cvt_kernel<<<dim3(BB * SS * DD / (256 * 8), 1), 256, 0, sB>>>(2, query, key, value);
    wt_kernel<<<dim3(32, 32, 1), 256, 0, sB>>>(2, Wq, Wk, Wv);
    proj_f16<<<dim3(8, 32, 1), 256, PJ_SMEM, sB>>>(2);
    cudaEventRecord(evB, sB);

    // Chain A (main stream): maskpack -> cvt(q,k) -> wt(q,k) -> proj(q,k) -> pass1
    maskpack_kernel<<<dim3(BB * SS * 64 / 256), 256>>>(mask);
    cvt_kernel<<<dim3(BB * SS * DD / (256 * 8), 2), 256>>>(0, query, key, value);
    wt_kernel<<<dim3(32, 32, 2), 256>>>(0, Wq, Wk, Wv);
    proj_f16<<<dim3(8, 32, 2), 256, PJ_SMEM>>>(0);
    pass1_kernel<<<dim3(8, 32), 256, P1_SMEM>>>();

    // Join: pass2 needs pass1 (A) and proj_v (B).
    cudaStreamWaitEvent(0, evB, 0);
    pass2_kernel<<<dim3(16, 32), 256, P2_SMEM>>>(attn);
    ln_kernel<<<dim3(BB * SS), 256>>>(query, gamma, beta, out);
}